// round 5
// baseline (speedup 1.0000x reference)
#include <cuda_runtime.h>
#include <cstdint>
#include <math.h>

#define NCn 100000
#define NEn 150000
#define EE  600000
#define H   128
#define D   64

typedef unsigned long long ull;

// ---------------- device scratch (static, no allocations) ----------------
__device__ float g_hc[NCn * H];
__device__ float g_he[NEn * H];
__device__ float g_hs[NEn * H];     // projected-src buffer (max NE rows)
__device__ float g_c1[NCn * H];
__device__ float g_e1[NEn * H];
__device__ float g_c2[NCn * H];
__device__ float g_e2[NEn * H];
__device__ float g_c3[NCn * D];
__device__ float g_e3[NEn * D];
__device__ float g_asrc6[6ul * NEn * 4];
__device__ float g_adst6[6ul * NEn * 4];
__device__ float g_Avs6[6 * 512];
__device__ float g_Avd6[6 * 512];
__device__ float g_Wsum[H * H];
__device__ float g_bsum[768];       // c1,e1,c2,e2 (128 each), c3,e3 (64 each)
__device__ float g_ew[EE * 4];      // GAT edge exp scratch
__device__ int   g_rowptr[6][NEn + 1];
__device__ int   g_col[6][EE];
__device__ int   g_cnt[6 * NEn];
__device__ int   g_bsums[6 * 256];

struct P6  { const int* p[6]; };
struct Nd6 { int nd[6]; };

// ---------------- f32x2 helpers ----------------
__device__ __forceinline__ ull pack2(float x, float y) {
    ull r; asm("mov.b64 %0,{%1,%2};" : "=l"(r) : "f"(x), "f"(y)); return r;
}
__device__ __forceinline__ ull dupf(float x) {
    ull r; asm("mov.b64 %0,{%1,%1};" : "=l"(r) : "f"(x)); return r;
}
__device__ __forceinline__ ull fma2(ull a, ull b, ull c) {
    ull d; asm("fma.rn.f32x2 %0,%1,%2,%3;" : "=l"(d) : "l"(a), "l"(b), "l"(c)); return d;
}
__device__ __forceinline__ void unpack2(ull v, float& x, float& y) {
    asm("mov.b64 {%0,%1},%2;" : "=f"(x), "=f"(y) : "l"(v));
}

// =====================================================================
// GEMM: C[N,NCOLS] = op(A)[N,128] * B[128,NCOLS]  (+C) (+bias) (relu)
// A pre-duplicated as f32x2 pairs in smem; 128-row tiles.
// GATHER=true: A-row r = mean over CSR neighbors of row r (SAGE fused).
// flags: bit0 = accumulate onto C, bit1 = relu at end. bias != null -> add.
// =====================================================================
#define TILE_M 128
template <int NCOLS, bool GATHER>
__global__ void __launch_bounds__(256) gemm128(const float* __restrict__ A,
                                               const int* __restrict__ rowptr,
                                               const int* __restrict__ colx,
                                               const float* __restrict__ B,
                                               float* __restrict__ C, int N,
                                               const float* __restrict__ bias,
                                               int flags) {
    extern __shared__ unsigned char smraw[];
    ull (*As2)[128] = reinterpret_cast<ull(*)[128]>(smraw);              // 128KB
    ull* Bs = reinterpret_cast<ull*>(smraw + TILE_M * 128 * sizeof(ull));

    const int tid = threadIdx.x;
    const int row0 = blockIdx.x * TILE_M;

    // ---- B fill: [128][NCOLS] -> packed col-pairs ----
    for (int i = tid; i < 128 * (NCOLS / 4); i += 256) {
        int k = i / (NCOLS / 4), cq = i % (NCOLS / 4);
        float4 f = __ldg(reinterpret_cast<const float4*>(B) + i);
        ulonglong2 v; v.x = pack2(f.x, f.y); v.y = pack2(f.z, f.w);
        *reinterpret_cast<ulonglong2*>(&Bs[k * (NCOLS / 2) + cq * 2]) = v;
    }
    // ---- A fill (duplicated pairs) ----
    if (!GATHER) {
        for (int i = tid; i < TILE_M * 32; i += 256) {
            int r = i >> 5, kq = i & 31;
            float4 f = make_float4(0.f, 0.f, 0.f, 0.f);
            if (row0 + r < N)
                f = __ldg(reinterpret_cast<const float4*>(A) + (size_t)(row0 + r) * 32 + kq);
            ulonglong2 v0; v0.x = dupf(f.x); v0.y = dupf(f.y);
            ulonglong2 v1; v1.x = dupf(f.z); v1.y = dupf(f.w);
            *reinterpret_cast<ulonglong2*>(&As2[r][kq * 4])     = v0;
            *reinterpret_cast<ulonglong2*>(&As2[r][kq * 4 + 2]) = v1;
        }
    } else {
        const int warp = tid >> 5, lane = tid & 31;
        for (int r = warp; r < TILE_M; r += 8) {
            int gr = row0 + r;
            float4 acc = make_float4(0.f, 0.f, 0.f, 0.f);
            if (gr < N) {
                int s0 = rowptr[gr], s1 = rowptr[gr + 1];
                for (int e = s0; e < s1; e++) {
                    int s = __ldg(&colx[e]);
                    float4 hv = __ldg(reinterpret_cast<const float4*>(A + (size_t)s * H) + lane);
                    acc.x += hv.x; acc.y += hv.y; acc.z += hv.z; acc.w += hv.w;
                }
                float sc = 1.f / fmaxf((float)(s1 - s0), 1.f);
                acc.x *= sc; acc.y *= sc; acc.z *= sc; acc.w *= sc;
            }
            ulonglong2 v0; v0.x = dupf(acc.x); v0.y = dupf(acc.y);
            ulonglong2 v1; v1.x = dupf(acc.z); v1.y = dupf(acc.w);
            *reinterpret_cast<ulonglong2*>(&As2[r][lane * 4])     = v0;
            *reinterpret_cast<ulonglong2*>(&As2[r][lane * 4 + 2]) = v1;
        }
    }
    __syncthreads();

    constexpr int TX = NCOLS / 4;     // 32 or 16
    constexpr int TY = 256 / TX;      // 8 or 16
    constexpr int RPT = TILE_M / TY;  // 16 or 8
    const int tx = tid % TX;
    const int rb = (tid / TX) * RPT;

    ull acc[RPT][2];
#pragma unroll
    for (int j = 0; j < RPT; j++) { acc[j][0] = 0ull; acc[j][1] = 0ull; }

#pragma unroll 4
    for (int kk = 0; kk < 128; kk += 2) {
        ulonglong2 b0 = *reinterpret_cast<const ulonglong2*>(&Bs[kk * (NCOLS / 2) + tx * 2]);
        ulonglong2 b1 = *reinterpret_cast<const ulonglong2*>(&Bs[(kk + 1) * (NCOLS / 2) + tx * 2]);
#pragma unroll
        for (int j = 0; j < RPT; j++) {
            ulonglong2 a = *reinterpret_cast<const ulonglong2*>(&As2[rb + j][kk]);
            acc[j][0] = fma2(a.x, b0.x, acc[j][0]);
            acc[j][1] = fma2(a.x, b0.y, acc[j][1]);
            acc[j][0] = fma2(a.y, b1.x, acc[j][0]);
            acc[j][1] = fma2(a.y, b1.y, acc[j][1]);
        }
    }

    float4 bv = make_float4(0.f, 0.f, 0.f, 0.f);
    if (bias) bv = __ldg(reinterpret_cast<const float4*>(bias) + tx);
#pragma unroll
    for (int j = 0; j < RPT; j++) {
        int r = row0 + rb + j;
        if (r < N) {
            float4 v;
            unpack2(acc[j][0], v.x, v.y);
            unpack2(acc[j][1], v.z, v.w);
            float4* cp = reinterpret_cast<float4*>(C + (size_t)r * NCOLS) + tx;
            if (flags & 1) {
                float4 o = *cp;
                v.x += o.x; v.y += o.y; v.z += o.z; v.w += o.w;
            }
            v.x += bv.x; v.y += bv.y; v.z += bv.z; v.w += bv.w;
            if (flags & 2) {
                v.x = fmaxf(v.x, 0.f); v.y = fmaxf(v.y, 0.f);
                v.z = fmaxf(v.z, 0.f); v.w = fmaxf(v.w, 0.f);
            }
            *cp = v;
        }
    }
}

// ---------------- batched CSR build ----------------
__global__ void zero_int(int* p, int n) {
    int i = blockIdx.x * blockDim.x + threadIdx.x;
    if (i < n) p[i] = 0;
}
__global__ void hist6(P6 ei, int* cnt) {
    int t = blockIdx.y;
    int i = blockIdx.x * blockDim.x + threadIdx.x;
    if (i < EE) atomicAdd(&cnt[t * NEn + __ldg(ei.p[t] + EE + i)], 1);
}
__global__ void scan_block6(const int* __restrict__ cnt, int* __restrict__ rowptr,
                            int* __restrict__ bsums, Nd6 nds) {
    __shared__ int sh[256];
    int t = blockIdx.y;
    int nd = nds.nd[t];
    if ((int)blockIdx.x * 1024 >= nd) return;
    const int* c = cnt + t * NEn;
    int* out = rowptr + t * (NEn + 1);
    int tid = threadIdx.x;
    int base = blockIdx.x * 1024 + tid * 4;
    int v0 = 0, v1 = 0, v2 = 0, v3 = 0;
    if (base + 0 < nd) v0 = c[base + 0];
    if (base + 1 < nd) v1 = c[base + 1];
    if (base + 2 < nd) v2 = c[base + 2];
    if (base + 3 < nd) v3 = c[base + 3];
    int ts = v0 + v1 + v2 + v3;
    int val = ts;
    sh[tid] = val; __syncthreads();
    for (int off = 1; off < 256; off <<= 1) {
        int tv = (tid >= off) ? sh[tid - off] : 0;
        __syncthreads();
        val += tv; sh[tid] = val; __syncthreads();
    }
    int excl = val - ts;
    if (base + 0 < nd) out[base + 0] = excl; excl += v0;
    if (base + 1 < nd) out[base + 1] = excl; excl += v1;
    if (base + 2 < nd) out[base + 2] = excl; excl += v2;
    if (base + 3 < nd) out[base + 3] = excl;
    if (tid == 255) bsums[t * 256 + blockIdx.x] = val;
}
__global__ void scan_top6(int* bsums, Nd6 nbs) {
    __shared__ int sh[256];
    int t = blockIdx.x;
    int n = nbs.nd[t];
    int* data = bsums + t * 256;
    int tid = threadIdx.x;
    int base = tid * 4;
    int v0 = 0, v1 = 0, v2 = 0, v3 = 0;
    if (base + 0 < n) v0 = data[base + 0];
    if (base + 1 < n) v1 = data[base + 1];
    if (base + 2 < n) v2 = data[base + 2];
    if (base + 3 < n) v3 = data[base + 3];
    int ts = v0 + v1 + v2 + v3;
    int val = ts;
    sh[tid] = val; __syncthreads();
    for (int off = 1; off < 256; off <<= 1) {
        int tv = (tid >= off) ? sh[tid - off] : 0;
        __syncthreads();
        val += tv; sh[tid] = val; __syncthreads();
    }
    int excl = val - ts;
    if (base + 0 < n) data[base + 0] = excl; excl += v0;
    if (base + 1 < n) data[base + 1] = excl; excl += v1;
    if (base + 2 < n) data[base + 2] = excl; excl += v2;
    if (base + 3 < n) data[base + 3] = excl;
}
__global__ void scan_add6(int* rowptr, const int* __restrict__ bsums, Nd6 nds) {
    int t = blockIdx.y;
    int nd = nds.nd[t];
    int i = blockIdx.x * blockDim.x + threadIdx.x;
    if (i < nd) rowptr[t * (NEn + 1) + i] += bsums[t * 256 + (i >> 10)];
    if (i == 0) rowptr[t * (NEn + 1) + nd] = EE;
}
__global__ void fill6(P6 ei, const int* __restrict__ rowptr, int* pos, int* col) {
    int t = blockIdx.y;
    int i = blockIdx.x * blockDim.x + threadIdx.x;
    if (i < EE) {
        int d = __ldg(ei.p[t] + EE + i);
        int s = __ldg(ei.p[t] + i);
        int p = rowptr[t * (NEn + 1) + d] + atomicAdd(&pos[t * NEn + d], 1);
        col[(size_t)t * EE + p] = s;
    }
}

// ---------------- encoders / small stuff ----------------
__global__ void encoder(const float* __restrict__ X, const float* __restrict__ W,
                        const float* __restrict__ b, float* __restrict__ out,
                        int N, int inF) {
    int t = blockIdx.x * blockDim.x + threadIdx.x;
    int row = t >> 5, cq = t & 31;
    if (row >= N) return;
    float4 acc = __ldg(reinterpret_cast<const float4*>(b) + cq);
    for (int k = 0; k < inF; k++) {
        float xv = __ldg(&X[(size_t)row * inF + k]);
        float4 wv = __ldg(reinterpret_cast<const float4*>(W) + k * 32 + cq);
        acc.x += xv * wv.x; acc.y += xv * wv.y; acc.z += xv * wv.z; acc.w += xv * wv.w;
    }
    acc.x = fmaxf(acc.x, 0.f); acc.y = fmaxf(acc.y, 0.f);
    acc.z = fmaxf(acc.z, 0.f); acc.w = fmaxf(acc.w, 0.f);
    reinterpret_cast<float4*>(out)[(size_t)row * 32 + cq] = acc;
}

// Av[t][k][h] = sum_j W[t][k][h*32+j]*a[t][h][j]  (6 blocks x 512 thr)
__global__ void compute_av6(const float* __restrict__ W6, const float* __restrict__ as6,
                            const float* __restrict__ ad6, float* Avs, float* Avd) {
    int t = blockIdx.x;
    const float* W = W6 + (size_t)t * H * H;
    const float* as = as6 + t * 128;
    const float* ad = ad6 + t * 128;
    int i = threadIdx.x;
    int k = i >> 2, h = i & 3;
    float sa = 0.f, sd = 0.f;
    for (int j = 0; j < 32; j++) {
        float w = W[k * H + h * 32 + j];
        sa += w * as[h * 32 + j];
        sd += w * ad[h * 32 + j];
    }
    Avs[t * 512 + k * 4 + h] = sa;
    Avd[t * 512 + k * 4 + h] = sd;
}

// batched matvec: out[n,4] = X[n,128] @ M[128,4], 12 segments via grid.y
struct MVArgs { const float* X; const float* M; float* out; int N; };
struct MV12 { MVArgs s[12]; };
__global__ void matvec_b(MV12 args) {
    MVArgs a = args.s[blockIdx.y];
    int gt = blockIdx.x * blockDim.x + threadIdx.x;
    int w = gt >> 5;
    if (w >= a.N) return;
    int lane = threadIdx.x & 31;
    float4 x = __ldg(reinterpret_cast<const float4*>(a.X) + (size_t)w * 32 + lane);
    float4 p = make_float4(0.f, 0.f, 0.f, 0.f);
    int k0 = lane * 4;
#pragma unroll
    for (int i = 0; i < 4; i++) {
        float4 m = __ldg(reinterpret_cast<const float4*>(a.M) + (k0 + i));
        float xv = (i == 0) ? x.x : (i == 1) ? x.y : (i == 2) ? x.z : x.w;
        p.x += xv * m.x; p.y += xv * m.y; p.z += xv * m.z; p.w += xv * m.w;
    }
    for (int off = 16; off; off >>= 1) {
        p.x += __shfl_down_sync(0xffffffffu, p.x, off);
        p.y += __shfl_down_sync(0xffffffffu, p.y, off);
        p.z += __shfl_down_sync(0xffffffffu, p.z, off);
        p.w += __shfl_down_sync(0xffffffffu, p.w, off);
    }
    if (lane == 0) reinterpret_cast<float4*>(a.out)[w] = p;
}

// GAT aggregation: warp per dst node; flags bit0=acc, bit1=bias+relu
__global__ void gat_agg(const int* __restrict__ rowptr, const int* __restrict__ col,
                        const float* __restrict__ hs, const float* __restrict__ asrc,
                        const float* __restrict__ adst, float* __restrict__ ew,
                        float* __restrict__ out, int nd, int flags,
                        const float* __restrict__ bias) {
    int w = (blockIdx.x * blockDim.x + threadIdx.x) >> 5;
    if (w >= nd) return;
    int lane = threadIdx.x & 31;
    int h = lane >> 3;
    int s0 = rowptr[w], s1 = rowptr[w + 1];
    float ad = __ldg(&adst[(size_t)w * 4 + h]);
    float den = 0.f;
    for (int e = s0; e < s1; e++) {
        int s = __ldg(&col[e]);
        float x = __ldg(&asrc[(size_t)s * 4 + h]) + ad;
        x = (x > 0.f) ? x : 0.2f * x;
        float ex = __expf(x);
        den += ex;
        if ((lane & 7) == 0) ew[(size_t)e * 4 + h] = ex;
    }
    __threadfence_block();
    __syncwarp();
    float rden = (s1 > s0) ? 1.f / den : 0.f;
    float4 acc = make_float4(0.f, 0.f, 0.f, 0.f);
    for (int e = s0; e < s1; e++) {
        int s = __ldg(&col[e]);
        float al = ew[(size_t)e * 4 + h] * rden;
        float4 hv = __ldg(reinterpret_cast<const float4*>(hs + (size_t)s * H) + lane);
        acc.x += al * hv.x; acc.y += al * hv.y; acc.z += al * hv.z; acc.w += al * hv.w;
    }
    float4* op = reinterpret_cast<float4*>(out + (size_t)w * H) + lane;
    if (flags & 1) {
        float4 o = *op;
        acc.x += o.x; acc.y += o.y; acc.z += o.z; acc.w += o.w;
    }
    if (flags & 2) {
        float4 b = __ldg(reinterpret_cast<const float4*>(bias) + lane);
        acc.x = fmaxf(acc.x + b.x, 0.f); acc.y = fmaxf(acc.y + b.y, 0.f);
        acc.z = fmaxf(acc.z + b.z, 0.f); acc.w = fmaxf(acc.w + b.w, 0.f);
    }
    *op = acc;
}

__global__ void add3(float* o, const float* a, const float* b, const float* c, int n) {
    int i = blockIdx.x * blockDim.x + threadIdx.x;
    if (i < n) o[i] = a[i] + b[i] + c[i];
}
__global__ void add2(float* o, const float* a, const float* b, int n) {
    int i = blockIdx.x * blockDim.x + threadIdx.x;
    if (i < n) o[i] = a[i] + b[i];
}
// all 6 bias-vector sums at once (1 block, 128 threads)
__global__ void bias_sums(const float* __restrict__ gatB, const float* __restrict__ s2bl,
                          const float* __restrict__ s3bl, float* __restrict__ o) {
    int t = threadIdx.x;  // 0..127
    o[t]       = gatB[t] + gatB[128 + t] + gatB[256 + t];
    o[128 + t] = gatB[384 + t] + gatB[512 + t] + gatB[640 + t];
    o[256 + t] = s2bl[t] + s2bl[128 + t] + s2bl[256 + t];
    o[384 + t] = s2bl[384 + t] + s2bl[512 + t] + s2bl[640 + t];
    if (t < 64) {
        o[512 + t] = s3bl[t] + s3bl[64 + t];
        o[576 + t] = s3bl[128 + t] + s3bl[192 + t];
    }
}

// L2-normalize rows of [N,64] -> out
__global__ void norm_out(const float* __restrict__ X, float* __restrict__ out, int N) {
    int gt = blockIdx.x * blockDim.x + threadIdx.x;
    int w = gt >> 5;
    if (w >= N) return;
    int lane = threadIdx.x & 31;
    float v0 = X[(size_t)w * 64 + lane];
    float v1 = X[(size_t)w * 64 + 32 + lane];
    float ss = v0 * v0 + v1 * v1;
    for (int off = 16; off; off >>= 1) ss += __shfl_xor_sync(0xffffffffu, ss, off);
    float sc = 1.f / fmaxf(sqrtf(ss), 1e-12f);
    out[(size_t)w * 64 + lane] = v0 * sc;
    out[(size_t)w * 64 + 32 + lane] = v1 * sc;
}

// ---------------- host ----------------
static inline int cdiv(int a, int b) { return (a + b - 1) / b; }

extern "C" void kernel_launch(void* const* d_in, const int* in_sizes, int n_in,
                              void* d_out, int out_size) {
    const float* xc    = (const float*)d_in[0];
    const float* xe    = (const float*)d_in[1];
    const float* Wc    = (const float*)d_in[2];
    const float* bc    = (const float*)d_in[3];
    const float* We    = (const float*)d_in[4];
    const float* be    = (const float*)d_in[5];
    const float* gatW  = (const float*)d_in[6];
    const float* gatAs = (const float*)d_in[7];
    const float* gatAd = (const float*)d_in[8];
    const float* gatB  = (const float*)d_in[9];
    const float* s2Wl  = (const float*)d_in[10];
    const float* s2bl  = (const float*)d_in[11];
    const float* s2Wr  = (const float*)d_in[12];
    const float* s3Wl  = (const float*)d_in[13];
    const float* s3bl  = (const float*)d_in[14];
    const float* s3Wr  = (const float*)d_in[15];
    float* out = (float*)d_out;

    void* p;
    cudaGetSymbolAddress(&p, g_hc);    float* hc   = (float*)p;
    cudaGetSymbolAddress(&p, g_he);    float* he   = (float*)p;
    cudaGetSymbolAddress(&p, g_hs);    float* hs   = (float*)p;
    cudaGetSymbolAddress(&p, g_c1);    float* c1   = (float*)p;
    cudaGetSymbolAddress(&p, g_e1);    float* e1   = (float*)p;
    cudaGetSymbolAddress(&p, g_c2);    float* c2   = (float*)p;
    cudaGetSymbolAddress(&p, g_e2);    float* e2   = (float*)p;
    cudaGetSymbolAddress(&p, g_c3);    float* c3   = (float*)p;
    cudaGetSymbolAddress(&p, g_e3);    float* e3   = (float*)p;
    cudaGetSymbolAddress(&p, g_asrc6); float* asrc6 = (float*)p;
    cudaGetSymbolAddress(&p, g_adst6); float* adst6 = (float*)p;
    cudaGetSymbolAddress(&p, g_Avs6);  float* Avs6 = (float*)p;
    cudaGetSymbolAddress(&p, g_Avd6);  float* Avd6 = (float*)p;
    cudaGetSymbolAddress(&p, g_Wsum);  float* Wsum = (float*)p;
    cudaGetSymbolAddress(&p, g_bsum);  float* bsum = (float*)p;
    cudaGetSymbolAddress(&p, g_ew);    float* ew   = (float*)p;
    cudaGetSymbolAddress(&p, g_rowptr); int* rowptr0 = (int*)p;
    cudaGetSymbolAddress(&p, g_col);    int* col0    = (int*)p;
    cudaGetSymbolAddress(&p, g_cnt);    int* cnt     = (int*)p;
    cudaGetSymbolAddress(&p, g_bsums);  int* bsums   = (int*)p;

    constexpr int SM128 = TILE_M * 128 * 8 + 128 * 64 * 8;  // 196608
    constexpr int SM64  = TILE_M * 128 * 8 + 128 * 32 * 8;  // 163840
    cudaFuncSetAttribute(gemm128<128, false>, cudaFuncAttributeMaxDynamicSharedMemorySize, SM128);
    cudaFuncSetAttribute(gemm128<128, true>,  cudaFuncAttributeMaxDynamicSharedMemorySize, SM128);
    cudaFuncSetAttribute(gemm128<64, false>,  cudaFuncAttributeMaxDynamicSharedMemorySize, SM64);
    cudaFuncSetAttribute(gemm128<64, true>,   cudaFuncAttributeMaxDynamicSharedMemorySize, SM64);

    // ---- batched CSR build ----
    P6 ei; Nd6 nds, nbs;
    const int ndArr[6] = {NCn, NCn, NCn, NEn, NEn, NEn};
    for (int t = 0; t < 6; t++) {
        ei.p[t] = (const int*)d_in[16 + t];
        nds.nd[t] = ndArr[t];
        nbs.nd[t] = cdiv(ndArr[t], 1024);
    }
    zero_int<<<cdiv(6 * NEn, 256), 256>>>(cnt, 6 * NEn);
    hist6<<<dim3(cdiv(EE, 256), 6), 256>>>(ei, cnt);
    scan_block6<<<dim3(cdiv(NEn, 1024), 6), 256>>>(cnt, rowptr0, bsums, nds);
    scan_top6<<<6, 256>>>(bsums, nbs);
    scan_add6<<<dim3(cdiv(NEn, 256), 6), 256>>>(rowptr0, bsums, nds);
    zero_int<<<cdiv(6 * NEn, 256), 256>>>(cnt, 6 * NEn);
    fill6<<<dim3(cdiv(EE, 256), 6), 256>>>(ei, rowptr0, cnt, col0);

    // ---- encoders + precomputed small tensors ----
    encoder<<<cdiv(NCn * 32, 256), 256>>>(xc, Wc, bc, hc, NCn, 5);
    encoder<<<cdiv(NEn * 32, 256), 256>>>(xe, We, be, he, NEn, 4);
    bias_sums<<<1, 128>>>(gatB, s2bl, s3bl, bsum);
    compute_av6<<<6, 512>>>(gatW, gatAs, gatAd, Avs6, Avd6);

    // batched attention matvecs: asrc (6) + adst (6)
    const float* xsArr[6] = {he, he, he, he, hc, hc};
    const float* xdArr[6] = {hc, hc, hc, he, he, he};
    const int nsArr[6] = {NEn, NEn, NEn, NEn, NCn, NCn};
    MV12 mv;
    for (int t = 0; t < 6; t++) {
        mv.s[t]     = {xsArr[t], Avs6 + t * 512, asrc6 + (size_t)t * NEn * 4, nsArr[t]};
        mv.s[6 + t] = {xdArr[t], Avd6 + t * 512, adst6 + (size_t)t * NEn * 4, ndArr[t]};
    }
    matvec_b<<<dim3(cdiv(NEn * 32, 256), 12), 256>>>(mv);

    // ---- Layer 1: GAT over 6 edge types ----
    const int HH = H * H;
    for (int t = 0; t < 6; t++) {
        const float* W = gatW + (size_t)t * HH;
        const float* xs = xsArr[t]; int ns = nsArr[t]; int nd = ndArr[t];
        float* dbuf = (t < 3) ? c1 : e1;
        int flags = (t == 0 || t == 3) ? 0 : 1;
        if (t == 2 || t == 5) flags |= 2;
        const float* bp = (t == 2) ? bsum : bsum + 128;
        gemm128<128, false><<<cdiv(ns, TILE_M), 256, SM128>>>(xs, nullptr, nullptr, W, hs, ns,
                                                              nullptr, 0);
        gat_agg<<<cdiv(nd * 32, 256), 256>>>(rowptr0 + t * (NEn + 1), col0 + (size_t)t * EE,
                                             hs, asrc6 + (size_t)t * NEn * 4,
                                             adst6 + (size_t)t * NEn * 4, ew, dbuf, nd, flags, bp);
    }

    // CSR handles
    const int* rp[6]; const int* cl[6];
    for (int t = 0; t < 6; t++) {
        rp[t] = rowptr0 + t * (NEn + 1);
        cl[t] = col0 + (size_t)t * EE;
    }

    // ---- Layer 2: SAGE (H -> H) with fused gather ----
    add3<<<cdiv(HH, 256), 256>>>(Wsum, s2Wr, s2Wr + HH, s2Wr + 2 * HH, HH);
    gemm128<128, true><<<cdiv(NCn, TILE_M), 256, SM128>>>(e1, rp[0], cl[0], s2Wl, c2, NCn,
                                                          bsum + 256, 0);
    gemm128<128, true><<<cdiv(NCn, TILE_M), 256, SM128>>>(e1, rp[1], cl[1], s2Wl + HH, c2, NCn,
                                                          nullptr, 1);
    gemm128<128, true><<<cdiv(NCn, TILE_M), 256, SM128>>>(e1, rp[2], cl[2], s2Wl + 2 * HH, c2, NCn,
                                                          nullptr, 1);
    gemm128<128, false><<<cdiv(NCn, TILE_M), 256, SM128>>>(c1, nullptr, nullptr, Wsum, c2, NCn,
                                                           nullptr, 1 | 2);

    add3<<<cdiv(HH, 256), 256>>>(Wsum, s2Wr + 3 * HH, s2Wr + 4 * HH, s2Wr + 5 * HH, HH);
    gemm128<128, true><<<cdiv(NEn, TILE_M), 256, SM128>>>(e1, rp[3], cl[3], s2Wl + 3 * HH, e2, NEn,
                                                          bsum + 384, 0);
    gemm128<128, true><<<cdiv(NEn, TILE_M), 256, SM128>>>(c1, rp[4], cl[4], s2Wl + 4 * HH, e2, NEn,
                                                          nullptr, 1);
    gemm128<128, true><<<cdiv(NEn, TILE_M), 256, SM128>>>(c1, rp[5], cl[5], s2Wl + 5 * HH, e2, NEn,
                                                          nullptr, 1);
    gemm128<128, false><<<cdiv(NEn, TILE_M), 256, SM128>>>(e1, nullptr, nullptr, Wsum, e2, NEn,
                                                           nullptr, 1 | 2);

    // ---- Layer 3: SAGE (H -> D) over [emp, board, codir, revemp] ----
    const int HD2 = H * D;
    add2<<<cdiv(HD2, 256), 256>>>(Wsum, s3Wr, s3Wr + HD2, HD2);
    gemm128<64, true><<<cdiv(NCn, TILE_M), 256, SM64>>>(e2, rp[0], cl[0], s3Wl, c3, NCn,
                                                        bsum + 512, 0);
    gemm128<64, true><<<cdiv(NCn, TILE_M), 256, SM64>>>(e2, rp[1], cl[1], s3Wl + HD2, c3, NCn,
                                                        nullptr, 1);
    gemm128<64, false><<<cdiv(NCn, TILE_M), 256, SM64>>>(c2, nullptr, nullptr, Wsum, c3, NCn,
                                                         nullptr, 1);
    norm_out<<<cdiv(NCn * 32, 256), 256>>>(c3, out, NCn);

    add2<<<cdiv(HD2, 256), 256>>>(Wsum, s3Wr + 2 * HD2, s3Wr + 3 * HD2, HD2);
    gemm128<64, true><<<cdiv(NEn, TILE_M), 256, SM64>>>(e2, rp[3], cl[3], s3Wl + 2 * HD2, e3, NEn,
                                                        bsum + 576, 0);
    gemm128<64, true><<<cdiv(NEn, TILE_M), 256, SM64>>>(c2, rp[4], cl[4], s3Wl + 3 * HD2, e3, NEn,
                                                        nullptr, 1);
    gemm128<64, false><<<cdiv(NEn, TILE_M), 256, SM64>>>(e2, nullptr, nullptr, Wsum, e3, NEn,
                                                         nullptr, 1);
    norm_out<<<cdiv(NEn * 32, 256), 256>>>(e3, out + (size_t)NCn * D, NEn);
}

// round 6
// speedup vs baseline: 1.5105x; 1.5105x over previous
#include <cuda_runtime.h>
#include <cstdint>
#include <math.h>

#define NCn 100000
#define NEn 150000
#define EE  600000
#define H   128
#define D   64

typedef unsigned long long ull;

// ---------------- device scratch (static, no allocations) ----------------
__device__ float g_hc[NCn * H];
__device__ float g_he[NEn * H];
__device__ float g_hs[NEn * H];     // projected-src buffer (max NE rows)
__device__ float g_mean[NEn * H];   // SAGE mean buffer
__device__ float g_c1[NCn * H];
__device__ float g_e1[NEn * H];
__device__ float g_c2[NCn * H];
__device__ float g_e2[NEn * H];
__device__ float g_c3[NCn * D];
__device__ float g_e3[NEn * D];
__device__ float g_asrc6[6ul * NEn * 4];
__device__ float g_adst6[6ul * NEn * 4];
__device__ float g_Avs6[6 * 512];
__device__ float g_Avd6[6 * 512];
__device__ float g_Wsum[H * H];
__device__ float g_bsum[768];       // c1,e1,c2,e2 (128 each), c3,e3 (64 each)
__device__ int   g_rowptr[6][NEn + 1];
__device__ int   g_col[6][EE];
__device__ int   g_cnt[6 * NEn];
__device__ int   g_bsums[6 * 256];

struct P6  { const int* p[6]; };
struct Nd6 { int nd[6]; };

// ---------------- f32x2 helpers ----------------
__device__ __forceinline__ ull dupf(float x) {
    ull r; asm("mov.b64 %0,{%1,%1};" : "=l"(r) : "f"(x)); return r;
}
__device__ __forceinline__ ull fma2(ull a, ull b, ull c) {
    ull d; asm("fma.rn.f32x2 %0,%1,%2,%3;" : "=l"(d) : "l"(a), "l"(b), "l"(c)); return d;
}
__device__ __forceinline__ void unpack2(ull v, float& x, float& y) {
    asm("mov.b64 {%0,%1},%2;" : "=f"(x), "=f"(y) : "l"(v));
}

// =====================================================================
// GEMM: C[N,NCOLS] = A[N,128] * B[128,NCOLS]  (+C) (+bias) (relu)
// f32x2 pair runs over ROWS: A stored k-major in smem as packed row-pairs
// (32KB), B scalar (64/32KB) -> 96/64KB smem, 2-3 blocks/SM.
// flags: bit0 = accumulate onto C, bit1 = relu. bias != null -> add.
// =====================================================================
template <int NCOLS>
__global__ void __launch_bounds__(256) gemm_rp(const float* __restrict__ A,
                                               const float* __restrict__ B,
                                               float* __restrict__ C, int N,
                                               const float* __restrict__ bias,
                                               int flags) {
    constexpr int TM = 64;
    extern __shared__ unsigned char smraw[];
    ull* As2p = reinterpret_cast<ull*>(smraw);                      // [128][TM/2]
    float* Bs = reinterpret_cast<float*>(smraw + 128 * (TM / 2) * 8);  // [128][NCOLS]

    const int tid = threadIdx.x;
    const int row0 = blockIdx.x * TM;

    // ---- B fill: straight copy [128][NCOLS] ----
    for (int i = tid; i < 128 * NCOLS / 4; i += 256)
        reinterpret_cast<float4*>(Bs)[i] = __ldg(reinterpret_cast<const float4*>(B) + i);

    // ---- A fill: k-major row-pair layout. float view: Af[k*TM + r] ----
    {
        float* Af = reinterpret_cast<float*>(As2p);
        for (int i = tid; i < TM * 32; i += 256) {
            int r = i & (TM - 1), kq = i >> 6;  // kq = float4 index along k
            float4 f = make_float4(0.f, 0.f, 0.f, 0.f);
            if (row0 + r < N)
                f = __ldg(reinterpret_cast<const float4*>(A) + (size_t)(row0 + r) * 32 + kq);
            Af[(kq * 4 + 0) * TM + r] = f.x;
            Af[(kq * 4 + 1) * TM + r] = f.y;
            Af[(kq * 4 + 2) * TM + r] = f.z;
            Af[(kq * 4 + 3) * TM + r] = f.w;
        }
    }
    __syncthreads();

    constexpr int TX = NCOLS / 4;   // 32 or 16
    constexpr int TY = 256 / TX;    // 8 or 16
    constexpr int RP = TM / TY / 2; // row-pairs per thread: 4 or 2
    const int tx = tid % TX;
    const int rp0 = (tid / TX) * RP;

    ull acc[RP][4];
#pragma unroll
    for (int j = 0; j < RP; j++)
#pragma unroll
        for (int c = 0; c < 4; c++) acc[j][c] = 0ull;

#pragma unroll 4
    for (int k = 0; k < 128; k++) {
        float4 b = *reinterpret_cast<const float4*>(&Bs[k * NCOLS + tx * 4]);
        ull b0 = dupf(b.x), b1 = dupf(b.y), b2 = dupf(b.z), b3 = dupf(b.w);
        const ull* ap = &As2p[k * (TM / 2) + rp0];
#pragma unroll
        for (int j = 0; j < RP; j++) {
            ull a = ap[j];
            acc[j][0] = fma2(a, b0, acc[j][0]);
            acc[j][1] = fma2(a, b1, acc[j][1]);
            acc[j][2] = fma2(a, b2, acc[j][2]);
            acc[j][3] = fma2(a, b3, acc[j][3]);
        }
    }

    float4 bv = make_float4(0.f, 0.f, 0.f, 0.f);
    if (bias) bv = __ldg(reinterpret_cast<const float4*>(bias) + tx);
#pragma unroll
    for (int j = 0; j < RP; j++) {
        int r = row0 + (rp0 + j) * 2;
        float4 v0, v1;
        unpack2(acc[j][0], v0.x, v1.x);
        unpack2(acc[j][1], v0.y, v1.y);
        unpack2(acc[j][2], v0.z, v1.z);
        unpack2(acc[j][3], v0.w, v1.w);
#pragma unroll
        for (int rr = 0; rr < 2; rr++) {
            int row = r + rr;
            if (row < N) {
                float4 v = rr ? v1 : v0;
                float4* cp = reinterpret_cast<float4*>(C + (size_t)row * NCOLS) + tx;
                if (flags & 1) {
                    float4 o = *cp;
                    v.x += o.x; v.y += o.y; v.z += o.z; v.w += o.w;
                }
                v.x += bv.x; v.y += bv.y; v.z += bv.z; v.w += bv.w;
                if (flags & 2) {
                    v.x = fmaxf(v.x, 0.f); v.y = fmaxf(v.y, 0.f);
                    v.z = fmaxf(v.z, 0.f); v.w = fmaxf(v.w, 0.f);
                }
                *cp = v;
            }
        }
    }
}

// ---------------- batched CSR build ----------------
__global__ void zero_int(int* p, int n) {
    int i = blockIdx.x * blockDim.x + threadIdx.x;
    if (i < n) p[i] = 0;
}
__global__ void hist6(P6 ei, int* cnt) {
    int t = blockIdx.y;
    int i = blockIdx.x * blockDim.x + threadIdx.x;
    if (i < EE) atomicAdd(&cnt[t * NEn + __ldg(ei.p[t] + EE + i)], 1);
}
__global__ void scan_block6(const int* __restrict__ cnt, int* __restrict__ rowptr,
                            int* __restrict__ bsums, Nd6 nds) {
    __shared__ int sh[256];
    int t = blockIdx.y;
    int nd = nds.nd[t];
    if ((int)blockIdx.x * 1024 >= nd) return;
    const int* c = cnt + t * NEn;
    int* out = rowptr + t * (NEn + 1);
    int tid = threadIdx.x;
    int base = blockIdx.x * 1024 + tid * 4;
    int v0 = 0, v1 = 0, v2 = 0, v3 = 0;
    if (base + 0 < nd) v0 = c[base + 0];
    if (base + 1 < nd) v1 = c[base + 1];
    if (base + 2 < nd) v2 = c[base + 2];
    if (base + 3 < nd) v3 = c[base + 3];
    int ts = v0 + v1 + v2 + v3;
    int val = ts;
    sh[tid] = val; __syncthreads();
    for (int off = 1; off < 256; off <<= 1) {
        int tv = (tid >= off) ? sh[tid - off] : 0;
        __syncthreads();
        val += tv; sh[tid] = val; __syncthreads();
    }
    int excl = val - ts;
    if (base + 0 < nd) out[base + 0] = excl; excl += v0;
    if (base + 1 < nd) out[base + 1] = excl; excl += v1;
    if (base + 2 < nd) out[base + 2] = excl; excl += v2;
    if (base + 3 < nd) out[base + 3] = excl;
    if (tid == 255) bsums[t * 256 + blockIdx.x] = val;
}
__global__ void scan_top6(int* bsums, Nd6 nbs) {
    __shared__ int sh[256];
    int t = blockIdx.x;
    int n = nbs.nd[t];
    int* data = bsums + t * 256;
    int tid = threadIdx.x;
    int base = tid * 4;
    int v0 = 0, v1 = 0, v2 = 0, v3 = 0;
    if (base + 0 < n) v0 = data[base + 0];
    if (base + 1 < n) v1 = data[base + 1];
    if (base + 2 < n) v2 = data[base + 2];
    if (base + 3 < n) v3 = data[base + 3];
    int ts = v0 + v1 + v2 + v3;
    int val = ts;
    sh[tid] = val; __syncthreads();
    for (int off = 1; off < 256; off <<= 1) {
        int tv = (tid >= off) ? sh[tid - off] : 0;
        __syncthreads();
        val += tv; sh[tid] = val; __syncthreads();
    }
    int excl = val - ts;
    if (base + 0 < n) data[base + 0] = excl; excl += v0;
    if (base + 1 < n) data[base + 1] = excl; excl += v1;
    if (base + 2 < n) data[base + 2] = excl; excl += v2;
    if (base + 3 < n) data[base + 3] = excl;
}
__global__ void scan_add6(int* rowptr, const int* __restrict__ bsums, Nd6 nds) {
    int t = blockIdx.y;
    int nd = nds.nd[t];
    int i = blockIdx.x * blockDim.x + threadIdx.x;
    if (i < nd) rowptr[t * (NEn + 1) + i] += bsums[t * 256 + (i >> 10)];
    if (i == 0) rowptr[t * (NEn + 1) + nd] = EE;
}
__global__ void fill6(P6 ei, const int* __restrict__ rowptr, int* pos, int* col) {
    int t = blockIdx.y;
    int i = blockIdx.x * blockDim.x + threadIdx.x;
    if (i < EE) {
        int d = __ldg(ei.p[t] + EE + i);
        int s = __ldg(ei.p[t] + i);
        int p = rowptr[t * (NEn + 1) + d] + atomicAdd(&pos[t * NEn + d], 1);
        col[(size_t)t * EE + p] = s;
    }
}

// ---------------- encoders / small stuff ----------------
__global__ void encoder(const float* __restrict__ X, const float* __restrict__ W,
                        const float* __restrict__ b, float* __restrict__ out,
                        int N, int inF) {
    int t = blockIdx.x * blockDim.x + threadIdx.x;
    int row = t >> 5, cq = t & 31;
    if (row >= N) return;
    float4 acc = __ldg(reinterpret_cast<const float4*>(b) + cq);
    for (int k = 0; k < inF; k++) {
        float xv = __ldg(&X[(size_t)row * inF + k]);
        float4 wv = __ldg(reinterpret_cast<const float4*>(W) + k * 32 + cq);
        acc.x += xv * wv.x; acc.y += xv * wv.y; acc.z += xv * wv.z; acc.w += xv * wv.w;
    }
    acc.x = fmaxf(acc.x, 0.f); acc.y = fmaxf(acc.y, 0.f);
    acc.z = fmaxf(acc.z, 0.f); acc.w = fmaxf(acc.w, 0.f);
    reinterpret_cast<float4*>(out)[(size_t)row * 32 + cq] = acc;
}

// Av[t][k][h] = sum_j W[t][k][h*32+j]*a[t][h][j]  (6 blocks x 512 thr)
__global__ void compute_av6(const float* __restrict__ W6, const float* __restrict__ as6,
                            const float* __restrict__ ad6, float* Avs, float* Avd) {
    int t = blockIdx.x;
    const float* W = W6 + (size_t)t * H * H;
    const float* as = as6 + t * 128;
    const float* ad = ad6 + t * 128;
    int i = threadIdx.x;
    int k = i >> 2, h = i & 3;
    float sa = 0.f, sd = 0.f;
    for (int j = 0; j < 32; j++) {
        float w = W[k * H + h * 32 + j];
        sa += w * as[h * 32 + j];
        sd += w * ad[h * 32 + j];
    }
    Avs[t * 512 + k * 4 + h] = sa;
    Avd[t * 512 + k * 4 + h] = sd;
}

// batched matvec: out[n,4] = X[n,128] @ M[128,4], 12 segments via grid.y
struct MVArgs { const float* X; const float* M; float* out; int N; };
struct MV12 { MVArgs s[12]; };
__global__ void matvec_b(MV12 args) {
    MVArgs a = args.s[blockIdx.y];
    int gt = blockIdx.x * blockDim.x + threadIdx.x;
    int w = gt >> 5;
    if (w >= a.N) return;
    int lane = threadIdx.x & 31;
    float4 x = __ldg(reinterpret_cast<const float4*>(a.X) + (size_t)w * 32 + lane);
    float4 p = make_float4(0.f, 0.f, 0.f, 0.f);
    int k0 = lane * 4;
#pragma unroll
    for (int i = 0; i < 4; i++) {
        float4 m = __ldg(reinterpret_cast<const float4*>(a.M) + (k0 + i));
        float xv = (i == 0) ? x.x : (i == 1) ? x.y : (i == 2) ? x.z : x.w;
        p.x += xv * m.x; p.y += xv * m.y; p.z += xv * m.z; p.w += xv * m.w;
    }
    for (int off = 16; off; off >>= 1) {
        p.x += __shfl_down_sync(0xffffffffu, p.x, off);
        p.y += __shfl_down_sync(0xffffffffu, p.y, off);
        p.z += __shfl_down_sync(0xffffffffu, p.z, off);
        p.w += __shfl_down_sync(0xffffffffu, p.w, off);
    }
    if (lane == 0) reinterpret_cast<float4*>(a.out)[w] = p;
}

// GAT aggregation: warp per dst node, in-register segment softmax (no max pass)
// flags bit0=acc, bit1=bias+relu
__global__ void gat_agg(const int* __restrict__ rowptr, const int* __restrict__ col,
                        const float* __restrict__ hs, const float* __restrict__ asrc,
                        const float* __restrict__ adst, float* __restrict__ out,
                        int nd, int flags, const float* __restrict__ bias) {
    int w = (blockIdx.x * blockDim.x + threadIdx.x) >> 5;
    if (w >= nd) return;
    int lane = threadIdx.x & 31;
    int h = lane >> 3;
    int s0 = rowptr[w], s1 = rowptr[w + 1];
    float ad = __ldg(&adst[(size_t)w * 4 + h]);
    float den = 0.f;
    for (int e = s0; e < s1; e++) {
        int s = __ldg(&col[e]);
        float x = __ldg(&asrc[(size_t)s * 4 + h]) + ad;
        x = (x > 0.f) ? x : 0.2f * x;
        den += __expf(x);
    }
    float rden = (s1 > s0) ? 1.f / den : 0.f;
    float4 acc = make_float4(0.f, 0.f, 0.f, 0.f);
    for (int e = s0; e < s1; e++) {
        int s = __ldg(&col[e]);
        float x = __ldg(&asrc[(size_t)s * 4 + h]) + ad;
        x = (x > 0.f) ? x : 0.2f * x;
        float al = __expf(x) * rden;
        float4 hv = __ldg(reinterpret_cast<const float4*>(hs + (size_t)s * H) + lane);
        acc.x += al * hv.x; acc.y += al * hv.y; acc.z += al * hv.z; acc.w += al * hv.w;
    }
    float4* op = reinterpret_cast<float4*>(out + (size_t)w * H) + lane;
    if (flags & 1) {
        float4 o = *op;
        acc.x += o.x; acc.y += o.y; acc.z += o.z; acc.w += o.w;
    }
    if (flags & 2) {
        float4 b = __ldg(reinterpret_cast<const float4*>(bias) + lane);
        acc.x = fmaxf(acc.x + b.x, 0.f); acc.y = fmaxf(acc.y + b.y, 0.f);
        acc.z = fmaxf(acc.z + b.z, 0.f); acc.w = fmaxf(acc.w + b.w, 0.f);
    }
    *op = acc;
}

// SAGE mean aggregation: warp per dst node
__global__ void sage_mean(const int* __restrict__ rowptr, const int* __restrict__ col,
                          const float* __restrict__ x, float* __restrict__ out, int nd) {
    int w = (blockIdx.x * blockDim.x + threadIdx.x) >> 5;
    if (w >= nd) return;
    int lane = threadIdx.x & 31;
    int s0 = rowptr[w], s1 = rowptr[w + 1];
    float4 acc = make_float4(0.f, 0.f, 0.f, 0.f);
    for (int e = s0; e < s1; e++) {
        int s = __ldg(&col[e]);
        float4 hv = __ldg(reinterpret_cast<const float4*>(x + (size_t)s * H) + lane);
        acc.x += hv.x; acc.y += hv.y; acc.z += hv.z; acc.w += hv.w;
    }
    float sc = 1.f / fmaxf((float)(s1 - s0), 1.f);
    acc.x *= sc; acc.y *= sc; acc.z *= sc; acc.w *= sc;
    reinterpret_cast<float4*>(out + (size_t)w * H)[lane] = acc;
}

__global__ void add3(float* o, const float* a, const float* b, const float* c, int n) {
    int i = blockIdx.x * blockDim.x + threadIdx.x;
    if (i < n) o[i] = a[i] + b[i] + c[i];
}
__global__ void add2(float* o, const float* a, const float* b, int n) {
    int i = blockIdx.x * blockDim.x + threadIdx.x;
    if (i < n) o[i] = a[i] + b[i];
}
// all 6 bias-vector sums at once (1 block, 128 threads)
__global__ void bias_sums(const float* __restrict__ gatB, const float* __restrict__ s2bl,
                          const float* __restrict__ s3bl, float* __restrict__ o) {
    int t = threadIdx.x;  // 0..127
    o[t]       = gatB[t] + gatB[128 + t] + gatB[256 + t];
    o[128 + t] = gatB[384 + t] + gatB[512 + t] + gatB[640 + t];
    o[256 + t] = s2bl[t] + s2bl[128 + t] + s2bl[256 + t];
    o[384 + t] = s2bl[384 + t] + s2bl[512 + t] + s2bl[640 + t];
    if (t < 64) {
        o[512 + t] = s3bl[t] + s3bl[64 + t];
        o[576 + t] = s3bl[128 + t] + s3bl[192 + t];
    }
}

// L2-normalize rows of [N,64] -> out
__global__ void norm_out(const float* __restrict__ X, float* __restrict__ out, int N) {
    int gt = blockIdx.x * blockDim.x + threadIdx.x;
    int w = gt >> 5;
    if (w >= N) return;
    int lane = threadIdx.x & 31;
    float v0 = X[(size_t)w * 64 + lane];
    float v1 = X[(size_t)w * 64 + 32 + lane];
    float ss = v0 * v0 + v1 * v1;
    for (int off = 16; off; off >>= 1) ss += __shfl_xor_sync(0xffffffffu, ss, off);
    float sc = 1.f / fmaxf(sqrtf(ss), 1e-12f);
    out[(size_t)w * 64 + lane] = v0 * sc;
    out[(size_t)w * 64 + 32 + lane] = v1 * sc;
}

// ---------------- host ----------------
static inline int cdiv(int a, int b) { return (a + b - 1) / b; }

extern "C" void kernel_launch(void* const* d_in, const int* in_sizes, int n_in,
                              void* d_out, int out_size) {
    const float* xc    = (const float*)d_in[0];
    const float* xe    = (const float*)d_in[1];
    const float* Wc    = (const float*)d_in[2];
    const float* bc    = (const float*)d_in[3];
    const float* We    = (const float*)d_in[4];
    const float* be    = (const float*)d_in[5];
    const float* gatW  = (const float*)d_in[6];
    const float* gatAs = (const float*)d_in[7];
    const float* gatAd = (const float*)d_in[8];
    const float* gatB  = (const float*)d_in[9];
    const float* s2Wl  = (const float*)d_in[10];
    const float* s2bl  = (const float*)d_in[11];
    const float* s2Wr  = (const float*)d_in[12];
    const float* s3Wl  = (const float*)d_in[13];
    const float* s3bl  = (const float*)d_in[14];
    const float* s3Wr  = (const float*)d_in[15];
    float* out = (float*)d_out;

    void* p;
    cudaGetSymbolAddress(&p, g_hc);    float* hc   = (float*)p;
    cudaGetSymbolAddress(&p, g_he);    float* he   = (float*)p;
    cudaGetSymbolAddress(&p, g_hs);    float* hs   = (float*)p;
    cudaGetSymbolAddress(&p, g_mean);  float* mean = (float*)p;
    cudaGetSymbolAddress(&p, g_c1);    float* c1   = (float*)p;
    cudaGetSymbolAddress(&p, g_e1);    float* e1   = (float*)p;
    cudaGetSymbolAddress(&p, g_c2);    float* c2   = (float*)p;
    cudaGetSymbolAddress(&p, g_e2);    float* e2   = (float*)p;
    cudaGetSymbolAddress(&p, g_c3);    float* c3   = (float*)p;
    cudaGetSymbolAddress(&p, g_e3);    float* e3   = (float*)p;
    cudaGetSymbolAddress(&p, g_asrc6); float* asrc6 = (float*)p;
    cudaGetSymbolAddress(&p, g_adst6); float* adst6 = (float*)p;
    cudaGetSymbolAddress(&p, g_Avs6);  float* Avs6 = (float*)p;
    cudaGetSymbolAddress(&p, g_Avd6);  float* Avd6 = (float*)p;
    cudaGetSymbolAddress(&p, g_Wsum);  float* Wsum = (float*)p;
    cudaGetSymbolAddress(&p, g_bsum);  float* bsum = (float*)p;
    cudaGetSymbolAddress(&p, g_rowptr); int* rowptr0 = (int*)p;
    cudaGetSymbolAddress(&p, g_col);    int* col0    = (int*)p;
    cudaGetSymbolAddress(&p, g_cnt);    int* cnt     = (int*)p;
    cudaGetSymbolAddress(&p, g_bsums);  int* bsums   = (int*)p;

    constexpr int SMA   = 128 * 32 * 8;        // 32768 (A row-pairs)
    constexpr int SM128 = SMA + 128 * 128 * 4; // 98304
    constexpr int SM64  = SMA + 128 * 64 * 4;  // 65536
    cudaFuncSetAttribute(gemm_rp<128>, cudaFuncAttributeMaxDynamicSharedMemorySize, SM128);
    cudaFuncSetAttribute(gemm_rp<64>,  cudaFuncAttributeMaxDynamicSharedMemorySize, SM64);

    // ---- batched CSR build ----
    P6 ei; Nd6 nds, nbs;
    const int ndArr[6] = {NCn, NCn, NCn, NEn, NEn, NEn};
    for (int t = 0; t < 6; t++) {
        ei.p[t] = (const int*)d_in[16 + t];
        nds.nd[t] = ndArr[t];
        nbs.nd[t] = cdiv(ndArr[t], 1024);
    }
    zero_int<<<cdiv(6 * NEn, 256), 256>>>(cnt, 6 * NEn);
    hist6<<<dim3(cdiv(EE, 256), 6), 256>>>(ei, cnt);
    scan_block6<<<dim3(cdiv(NEn, 1024), 6), 256>>>(cnt, rowptr0, bsums, nds);
    scan_top6<<<6, 256>>>(bsums, nbs);
    scan_add6<<<dim3(cdiv(NEn, 256), 6), 256>>>(rowptr0, bsums, nds);
    zero_int<<<cdiv(6 * NEn, 256), 256>>>(cnt, 6 * NEn);
    fill6<<<dim3(cdiv(EE, 256), 6), 256>>>(ei, rowptr0, cnt, col0);

    // ---- encoders + precomputed small tensors ----
    encoder<<<cdiv(NCn * 32, 256), 256>>>(xc, Wc, bc, hc, NCn, 5);
    encoder<<<cdiv(NEn * 32, 256), 256>>>(xe, We, be, he, NEn, 4);
    bias_sums<<<1, 128>>>(gatB, s2bl, s3bl, bsum);
    compute_av6<<<6, 512>>>(gatW, gatAs, gatAd, Avs6, Avd6);

    // batched attention matvecs: asrc (6) + adst (6)
    const float* xsArr[6] = {he, he, he, he, hc, hc};
    const float* xdArr[6] = {hc, hc, hc, he, he, he};
    const int nsArr[6] = {NEn, NEn, NEn, NEn, NCn, NCn};
    MV12 mv;
    for (int t = 0; t < 6; t++) {
        mv.s[t]     = {xsArr[t], Avs6 + t * 512, asrc6 + (size_t)t * NEn * 4, nsArr[t]};
        mv.s[6 + t] = {xdArr[t], Avd6 + t * 512, adst6 + (size_t)t * NEn * 4, ndArr[t]};
    }
    matvec_b<<<dim3(cdiv(NEn * 32, 256), 12), 256>>>(mv);

    // ---- Layer 1: GAT over 6 edge types ----
    const int HH = H * H;
    for (int t = 0; t < 6; t++) {
        const float* W = gatW + (size_t)t * HH;
        const float* xs = xsArr[t]; int ns = nsArr[t]; int nd = ndArr[t];
        float* dbuf = (t < 3) ? c1 : e1;
        int flags = (t == 0 || t == 3) ? 0 : 1;
        if (t == 2 || t == 5) flags |= 2;
        const float* bp = (t == 2) ? bsum : bsum + 128;
        gemm_rp<128><<<cdiv(ns, 64), 256, SM128>>>(xs, W, hs, ns, nullptr, 0);
        gat_agg<<<cdiv(nd * 32, 256), 256>>>(rowptr0 + t * (NEn + 1), col0 + (size_t)t * EE,
                                             hs, asrc6 + (size_t)t * NEn * 4,
                                             adst6 + (size_t)t * NEn * 4, dbuf, nd, flags, bp);
    }

    // CSR handles
    const int* rp[6]; const int* cl[6];
    for (int t = 0; t < 6; t++) {
        rp[t] = rowptr0 + t * (NEn + 1);
        cl[t] = col0 + (size_t)t * EE;
    }

    // ---- Layer 2: SAGE (H -> H) ----
    add3<<<cdiv(HH, 256), 256>>>(Wsum, s2Wr, s2Wr + HH, s2Wr + 2 * HH, HH);
    sage_mean<<<cdiv(NCn * 32, 256), 256>>>(rp[0], cl[0], e1, mean, NCn);
    gemm_rp<128><<<cdiv(NCn, 64), 256, SM128>>>(mean, s2Wl, c2, NCn, bsum + 256, 0);
    sage_mean<<<cdiv(NCn * 32, 256), 256>>>(rp[1], cl[1], e1, mean, NCn);
    gemm_rp<128><<<cdiv(NCn, 64), 256, SM128>>>(mean, s2Wl + HH, c2, NCn, nullptr, 1);
    sage_mean<<<cdiv(NCn * 32, 256), 256>>>(rp[2], cl[2], e1, mean, NCn);
    gemm_rp<128><<<cdiv(NCn, 64), 256, SM128>>>(mean, s2Wl + 2 * HH, c2, NCn, nullptr, 1);
    gemm_rp<128><<<cdiv(NCn, 64), 256, SM128>>>(c1, Wsum, c2, NCn, nullptr, 1 | 2);

    add3<<<cdiv(HH, 256), 256>>>(Wsum, s2Wr + 3 * HH, s2Wr + 4 * HH, s2Wr + 5 * HH, HH);
    sage_mean<<<cdiv(NEn * 32, 256), 256>>>(rp[3], cl[3], e1, mean, NEn);
    gemm_rp<128><<<cdiv(NEn, 64), 256, SM128>>>(mean, s2Wl + 3 * HH, e2, NEn, bsum + 384, 0);
    sage_mean<<<cdiv(NEn * 32, 256), 256>>>(rp[4], cl[4], c1, mean, NEn);
    gemm_rp<128><<<cdiv(NEn, 64), 256, SM128>>>(mean, s2Wl + 4 * HH, e2, NEn, nullptr, 1);
    sage_mean<<<cdiv(NEn * 32, 256), 256>>>(rp[5], cl[5], c1, mean, NEn);
    gemm_rp<128><<<cdiv(NEn, 64), 256, SM128>>>(mean, s2Wl + 5 * HH, e2, NEn, nullptr, 1);
    gemm_rp<128><<<cdiv(NEn, 64), 256, SM128>>>(e1, Wsum, e2, NEn, nullptr, 1 | 2);

    // ---- Layer 3: SAGE (H -> D) over [emp, board, codir, revemp] ----
    const int HD2 = H * D;
    add2<<<cdiv(HD2, 256), 256>>>(Wsum, s3Wr, s3Wr + HD2, HD2);
    sage_mean<<<cdiv(NCn * 32, 256), 256>>>(rp[0], cl[0], e2, mean, NCn);
    gemm_rp<64><<<cdiv(NCn, 64), 256, SM64>>>(mean, s3Wl, c3, NCn, bsum + 512, 0);
    sage_mean<<<cdiv(NCn * 32, 256), 256>>>(rp[1], cl[1], e2, mean, NCn);
    gemm_rp<64><<<cdiv(NCn, 64), 256, SM64>>>(mean, s3Wl + HD2, c3, NCn, nullptr, 1);
    gemm_rp<64><<<cdiv(NCn, 64), 256, SM64>>>(c2, Wsum, c3, NCn, nullptr, 1);
    norm_out<<<cdiv(NCn * 32, 256), 256>>>(c3, out, NCn);

    add2<<<cdiv(HD2, 256), 256>>>(Wsum, s3Wr + 2 * HD2, s3Wr + 3 * HD2, HD2);
    sage_mean<<<cdiv(NEn * 32, 256), 256>>>(rp[3], cl[3], e2, mean, NEn);
    gemm_rp<64><<<cdiv(NEn, 64), 256, SM64>>>(mean, s3Wl + 2 * HD2, e3, NEn, bsum + 576, 0);
    sage_mean<<<cdiv(NEn * 32, 256), 256>>>(rp[4], cl[4], c2, mean, NEn);
    gemm_rp<64><<<cdiv(NEn, 64), 256, SM64>>>(mean, s3Wl + 3 * HD2, e3, NEn, nullptr, 1);
    gemm_rp<64><<<cdiv(NEn, 64), 256, SM64>>>(e2, Wsum, e3, NEn, nullptr, 1);
    norm_out<<<cdiv(NEn * 32, 256), 256>>>(e3, out + (size_t)NCn * D, NEn);
}

// round 7
// speedup vs baseline: 1.6864x; 1.1165x over previous
#include <cuda_runtime.h>
#include <cstdint>
#include <math.h>

#define NCn 100000
#define NEn 150000
#define EE  600000
#define H   128
#define D   64

typedef unsigned long long ull;

// ---------------- device scratch (static, no allocations) ----------------
__device__ float g_hc[NCn * H];
__device__ float g_he[NEn * H];
__device__ float g_hs0[NEn * H];
__device__ float g_hs1[NEn * H];
__device__ float g_c1[NCn * H];
__device__ float g_e1[NEn * H];
__device__ float g_c2[NCn * H];
__device__ float g_e2[NEn * H];
__device__ float g_c3[NCn * D];
__device__ float g_e3[NEn * D];
__device__ float g_mcC[(size_t)NCn * 384];   // concat mean buffer (c side)
__device__ float g_mcE[(size_t)NEn * 384];   // concat mean buffer (e side)
__device__ float g_asrc6[6ul * NEn * 4];
__device__ float g_adst6[6ul * NEn * 4];
__device__ float g_Avs6[6 * 512];
__device__ float g_Avd6[6 * 512];
__device__ float g_bsum[768];                // c1,e1,c2,e2 (128), c3,e3 (64)
__device__ float g_Bc2[512 * 128];
__device__ float g_Be2[512 * 128];
__device__ float g_Bc3[384 * 64];
__device__ float g_Be3[384 * 64];
__device__ int   g_rowptr[6][NEn + 1];
__device__ int   g_col[6][EE];
__device__ int   g_cnt[6 * NEn];
__device__ int   g_bsums[6 * 256];

struct P6  { const int* p[6]; };
struct Nd6 { int nd[6]; };
struct MG  { const int* rp[3]; const int* cl[3]; const float* src[3]; };

// ---------------- f32x2 helpers ----------------
__device__ __forceinline__ ull dupf(float x) {
    ull r; asm("mov.b64 %0,{%1,%1};" : "=l"(r) : "f"(x)); return r;
}
__device__ __forceinline__ ull fma2(ull a, ull b, ull c) {
    ull d; asm("fma.rn.f32x2 %0,%1,%2,%3;" : "=l"(d) : "l"(a), "l"(b), "l"(c)); return d;
}
__device__ __forceinline__ void unpack2(ull v, float& x, float& y) {
    asm("mov.b64 {%0,%1},%2;" : "=f"(x), "=f"(y) : "l"(v));
}

// =====================================================================
// GEMM: C[N,NCOLS] = [Acat | Aself][N, CHUNKS*128] * B[CHUNKS*128, NCOLS]
// Acat holds first CHUNKS-1 column-chunks (row stride (CHUNKS-1)*128),
// Aself the last chunk (row stride 128). CHUNKS=1 -> Aself only.
// A in smem k-major as packed row-pairs (f32x2 over ROWS). 64-row tiles.
// flags: bit1 = relu. bias != null -> add.
// =====================================================================
template <int NCOLS, int CHUNKS>
__global__ void __launch_bounds__(256) gemmk(const float* __restrict__ Acat,
                                             const float* __restrict__ Aself,
                                             const float* __restrict__ B,
                                             float* __restrict__ C, int N,
                                             const float* __restrict__ bias,
                                             int flags) {
    constexpr int TM = 64;
    extern __shared__ unsigned char smraw[];
    ull* As2p = reinterpret_cast<ull*>(smraw);                         // [128][TM/2]
    float* Bs = reinterpret_cast<float*>(smraw + 128 * (TM / 2) * 8);  // [128][NCOLS]

    const int tid = threadIdx.x;
    const int row0 = blockIdx.x * TM;

    constexpr int TX = NCOLS / 4;   // 32 or 16
    constexpr int TY = 256 / TX;    // 8 or 16
    constexpr int RP = TM / TY / 2; // row-pairs per thread: 4 or 2
    const int tx = tid % TX;
    const int rp0 = (tid / TX) * RP;

    ull acc[RP][4];
#pragma unroll
    for (int j = 0; j < RP; j++)
#pragma unroll
        for (int c = 0; c < 4; c++) acc[j][c] = 0ull;

    for (int ch = 0; ch < CHUNKS; ch++) {
        if (ch > 0) __syncthreads();  // readers of previous chunk done
        // ---- B fill for this chunk ----
        const float* Bp = B + (size_t)ch * 128 * NCOLS;
        for (int i = tid; i < 128 * NCOLS / 4; i += 256)
            reinterpret_cast<float4*>(Bs)[i] = __ldg(reinterpret_cast<const float4*>(Bp) + i);
        // ---- A fill: k-major row-pair layout ----
        {
            const float* Asrc; int strideA;
            if (ch == CHUNKS - 1) { Asrc = Aself; strideA = 128; }
            else { Asrc = Acat + ch * 128; strideA = (CHUNKS - 1) * 128; }
            float* Af = reinterpret_cast<float*>(As2p);
            for (int i = tid; i < TM * 32; i += 256) {
                int r = i & (TM - 1), kq = i >> 6;
                float4 f = make_float4(0.f, 0.f, 0.f, 0.f);
                if (row0 + r < N)
                    f = __ldg(reinterpret_cast<const float4*>(
                            Asrc + (size_t)(row0 + r) * strideA) + kq);
                Af[(kq * 4 + 0) * TM + r] = f.x;
                Af[(kq * 4 + 1) * TM + r] = f.y;
                Af[(kq * 4 + 2) * TM + r] = f.z;
                Af[(kq * 4 + 3) * TM + r] = f.w;
            }
        }
        __syncthreads();

#pragma unroll 4
        for (int k = 0; k < 128; k++) {
            float4 b = *reinterpret_cast<const float4*>(&Bs[k * NCOLS + tx * 4]);
            ull b0 = dupf(b.x), b1 = dupf(b.y), b2 = dupf(b.z), b3 = dupf(b.w);
            const ull* ap = &As2p[k * (TM / 2) + rp0];
#pragma unroll
            for (int j = 0; j < RP; j++) {
                ull a = ap[j];
                acc[j][0] = fma2(a, b0, acc[j][0]);
                acc[j][1] = fma2(a, b1, acc[j][1]);
                acc[j][2] = fma2(a, b2, acc[j][2]);
                acc[j][3] = fma2(a, b3, acc[j][3]);
            }
        }
    }

    float4 bv = make_float4(0.f, 0.f, 0.f, 0.f);
    if (bias) bv = __ldg(reinterpret_cast<const float4*>(bias) + tx);
#pragma unroll
    for (int j = 0; j < RP; j++) {
        int r = row0 + (rp0 + j) * 2;
        float4 v0, v1;
        unpack2(acc[j][0], v0.x, v1.x);
        unpack2(acc[j][1], v0.y, v1.y);
        unpack2(acc[j][2], v0.z, v1.z);
        unpack2(acc[j][3], v0.w, v1.w);
#pragma unroll
        for (int rr = 0; rr < 2; rr++) {
            int row = r + rr;
            if (row < N) {
                float4 v = rr ? v1 : v0;
                v.x += bv.x; v.y += bv.y; v.z += bv.z; v.w += bv.w;
                if (flags & 2) {
                    v.x = fmaxf(v.x, 0.f); v.y = fmaxf(v.y, 0.f);
                    v.z = fmaxf(v.z, 0.f); v.w = fmaxf(v.w, 0.f);
                }
                reinterpret_cast<float4*>(C + (size_t)row * NCOLS)[tx] = v;
            }
        }
    }
}

// ---------------- batched CSR build ----------------
__global__ void zero_int(int* p, int n) {
    int i = blockIdx.x * blockDim.x + threadIdx.x;
    if (i < n) p[i] = 0;
}
__global__ void hist6(P6 ei, int* cnt) {
    int t = blockIdx.y;
    int i = blockIdx.x * blockDim.x + threadIdx.x;
    if (i < EE) atomicAdd(&cnt[t * NEn + __ldg(ei.p[t] + EE + i)], 1);
}
__global__ void scan_block6(const int* __restrict__ cnt, int* __restrict__ rowptr,
                            int* __restrict__ bsums, Nd6 nds) {
    __shared__ int sh[256];
    int t = blockIdx.y;
    int nd = nds.nd[t];
    if ((int)blockIdx.x * 1024 >= nd) return;
    const int* c = cnt + t * NEn;
    int* out = rowptr + t * (NEn + 1);
    int tid = threadIdx.x;
    int base = blockIdx.x * 1024 + tid * 4;
    int v0 = 0, v1 = 0, v2 = 0, v3 = 0;
    if (base + 0 < nd) v0 = c[base + 0];
    if (base + 1 < nd) v1 = c[base + 1];
    if (base + 2 < nd) v2 = c[base + 2];
    if (base + 3 < nd) v3 = c[base + 3];
    int ts = v0 + v1 + v2 + v3;
    int val = ts;
    sh[tid] = val; __syncthreads();
    for (int off = 1; off < 256; off <<= 1) {
        int tv = (tid >= off) ? sh[tid - off] : 0;
        __syncthreads();
        val += tv; sh[tid] = val; __syncthreads();
    }
    int excl = val - ts;
    if (base + 0 < nd) out[base + 0] = excl; excl += v0;
    if (base + 1 < nd) out[base + 1] = excl; excl += v1;
    if (base + 2 < nd) out[base + 2] = excl; excl += v2;
    if (base + 3 < nd) out[base + 3] = excl;
    if (tid == 255) bsums[t * 256 + blockIdx.x] = val;
}
__global__ void scan_top6(int* bsums, Nd6 nbs) {
    __shared__ int sh[256];
    int t = blockIdx.x;
    int n = nbs.nd[t];
    int* data = bsums + t * 256;
    int tid = threadIdx.x;
    int base = tid * 4;
    int v0 = 0, v1 = 0, v2 = 0, v3 = 0;
    if (base + 0 < n) v0 = data[base + 0];
    if (base + 1 < n) v1 = data[base + 1];
    if (base + 2 < n) v2 = data[base + 2];
    if (base + 3 < n) v3 = data[base + 3];
    int ts = v0 + v1 + v2 + v3;
    int val = ts;
    sh[tid] = val; __syncthreads();
    for (int off = 1; off < 256; off <<= 1) {
        int tv = (tid >= off) ? sh[tid - off] : 0;
        __syncthreads();
        val += tv; sh[tid] = val; __syncthreads();
    }
    int excl = val - ts;
    if (base + 0 < n) data[base + 0] = excl; excl += v0;
    if (base + 1 < n) data[base + 1] = excl; excl += v1;
    if (base + 2 < n) data[base + 2] = excl; excl += v2;
    if (base + 3 < n) data[base + 3] = excl;
}
__global__ void scan_add6(int* rowptr, const int* __restrict__ bsums, Nd6 nds) {
    int t = blockIdx.y;
    int nd = nds.nd[t];
    int i = blockIdx.x * blockDim.x + threadIdx.x;
    if (i < nd) rowptr[t * (NEn + 1) + i] += bsums[t * 256 + (i >> 10)];
    if (i == 0) rowptr[t * (NEn + 1) + nd] = EE;
}
__global__ void fill6(P6 ei, const int* __restrict__ rowptr, int* pos, int* col) {
    int t = blockIdx.y;
    int i = blockIdx.x * blockDim.x + threadIdx.x;
    if (i < EE) {
        int d = __ldg(ei.p[t] + EE + i);
        int s = __ldg(ei.p[t] + i);
        int p = rowptr[t * (NEn + 1) + d] + atomicAdd(&pos[t * NEn + d], 1);
        col[(size_t)t * EE + p] = s;
    }
}

// ---------------- encoders / small stuff ----------------
__global__ void encoder(const float* __restrict__ X, const float* __restrict__ W,
                        const float* __restrict__ b, float* __restrict__ out,
                        int N, int inF) {
    int t = blockIdx.x * blockDim.x + threadIdx.x;
    int row = t >> 5, cq = t & 31;
    if (row >= N) return;
    float4 acc = __ldg(reinterpret_cast<const float4*>(b) + cq);
    for (int k = 0; k < inF; k++) {
        float xv = __ldg(&X[(size_t)row * inF + k]);
        float4 wv = __ldg(reinterpret_cast<const float4*>(W) + k * 32 + cq);
        acc.x += xv * wv.x; acc.y += xv * wv.y; acc.z += xv * wv.z; acc.w += xv * wv.w;
    }
    acc.x = fmaxf(acc.x, 0.f); acc.y = fmaxf(acc.y, 0.f);
    acc.z = fmaxf(acc.z, 0.f); acc.w = fmaxf(acc.w, 0.f);
    reinterpret_cast<float4*>(out)[(size_t)row * 32 + cq] = acc;
}

__global__ void compute_av6(const float* __restrict__ W6, const float* __restrict__ as6,
                            const float* __restrict__ ad6, float* Avs, float* Avd) {
    int t = blockIdx.x;
    const float* W = W6 + (size_t)t * H * H;
    const float* as = as6 + t * 128;
    const float* ad = ad6 + t * 128;
    int i = threadIdx.x;
    int k = i >> 2, h = i & 3;
    float sa = 0.f, sd = 0.f;
    for (int j = 0; j < 32; j++) {
        float w = W[k * H + h * 32 + j];
        sa += w * as[h * 32 + j];
        sd += w * ad[h * 32 + j];
    }
    Avs[t * 512 + k * 4 + h] = sa;
    Avd[t * 512 + k * 4 + h] = sd;
}

struct MVArgs { const float* X; const float* M; float* out; int N; };
struct MV12 { MVArgs s[12]; };
__global__ void matvec_b(MV12 args) {
    MVArgs a = args.s[blockIdx.y];
    int gt = blockIdx.x * blockDim.x + threadIdx.x;
    int w = gt >> 5;
    if (w >= a.N) return;
    int lane = threadIdx.x & 31;
    float4 x = __ldg(reinterpret_cast<const float4*>(a.X) + (size_t)w * 32 + lane);
    float4 p = make_float4(0.f, 0.f, 0.f, 0.f);
    int k0 = lane * 4;
#pragma unroll
    for (int i = 0; i < 4; i++) {
        float4 m = __ldg(reinterpret_cast<const float4*>(a.M) + (k0 + i));
        float xv = (i == 0) ? x.x : (i == 1) ? x.y : (i == 2) ? x.z : x.w;
        p.x += xv * m.x; p.y += xv * m.y; p.z += xv * m.z; p.w += xv * m.w;
    }
    for (int off = 16; off; off >>= 1) {
        p.x += __shfl_down_sync(0xffffffffu, p.x, off);
        p.y += __shfl_down_sync(0xffffffffu, p.y, off);
        p.z += __shfl_down_sync(0xffffffffu, p.z, off);
        p.w += __shfl_down_sync(0xffffffffu, p.w, off);
    }
    if (lane == 0) reinterpret_cast<float4*>(a.out)[w] = p;
}

// GAT aggregation: warp per dst node; flags bit0=acc, bit1=bias+relu
__global__ void gat_agg(const int* __restrict__ rowptr, const int* __restrict__ col,
                        const float* __restrict__ hs, const float* __restrict__ asrc,
                        const float* __restrict__ adst, float* __restrict__ out,
                        int nd, int flags, const float* __restrict__ bias) {
    int w = (blockIdx.x * blockDim.x + threadIdx.x) >> 5;
    if (w >= nd) return;
    int lane = threadIdx.x & 31;
    int h = lane >> 3;
    int s0 = rowptr[w], s1 = rowptr[w + 1];
    float ad = __ldg(&adst[(size_t)w * 4 + h]);
    float den = 0.f;
    for (int e = s0; e < s1; e++) {
        int s = __ldg(&col[e]);
        float x = __ldg(&asrc[(size_t)s * 4 + h]) + ad;
        x = (x > 0.f) ? x : 0.2f * x;
        den += __expf(x);
    }
    float rden = (s1 > s0) ? 1.f / den : 0.f;
    float4 acc = make_float4(0.f, 0.f, 0.f, 0.f);
    for (int e = s0; e < s1; e++) {
        int s = __ldg(&col[e]);
        float x = __ldg(&asrc[(size_t)s * 4 + h]) + ad;
        x = (x > 0.f) ? x : 0.2f * x;
        float al = __expf(x) * rden;
        float4 hv = __ldg(reinterpret_cast<const float4*>(hs + (size_t)s * H) + lane);
        acc.x += al * hv.x; acc.y += al * hv.y; acc.z += al * hv.z; acc.w += al * hv.w;
    }
    float4* op = reinterpret_cast<float4*>(out + (size_t)w * H) + lane;
    if (flags & 1) {
        float4 o = *op;
        acc.x += o.x; acc.y += o.y; acc.z += o.z; acc.w += o.w;
    }
    if (flags & 2) {
        float4 b = __ldg(reinterpret_cast<const float4*>(bias) + lane);
        acc.x = fmaxf(acc.x + b.x, 0.f); acc.y = fmaxf(acc.y + b.y, 0.f);
        acc.z = fmaxf(acc.z + b.z, 0.f); acc.w = fmaxf(acc.w + b.w, 0.f);
    }
    *op = acc;
}

// merged SAGE mean: warp per dst node, nt types -> concat output [nd, nt*128]
__global__ void mean3(MG g, int nt, int nd, float* __restrict__ outCat) {
    int w = (blockIdx.x * blockDim.x + threadIdx.x) >> 5;
    if (w >= nd) return;
    int lane = threadIdx.x & 31;
    int stride = nt * 128;
    for (int tt = 0; tt < nt; tt++) {
        int s0 = g.rp[tt][w], s1 = g.rp[tt][w + 1];
        const float* src = g.src[tt];
        const int* col = g.cl[tt];
        float4 acc = make_float4(0.f, 0.f, 0.f, 0.f);
        for (int e = s0; e < s1; e++) {
            int s = __ldg(&col[e]);
            float4 hv = __ldg(reinterpret_cast<const float4*>(src + (size_t)s * H) + lane);
            acc.x += hv.x; acc.y += hv.y; acc.z += hv.z; acc.w += hv.w;
        }
        float sc = 1.f / fmaxf((float)(s1 - s0), 1.f);
        acc.x *= sc; acc.y *= sc; acc.z *= sc; acc.w *= sc;
        *reinterpret_cast<float4*>(outCat + (size_t)w * stride + tt * 128 + lane * 4) = acc;
    }
}

// B-concat prep: out[(nt+1)*128, ncols] = [Wl_0; ...; Wl_{nt-1}; sum_j Wr_j]
__global__ void bcat(const float* __restrict__ Wl, const float* __restrict__ Wr,
                     int nt, int ncols, float* __restrict__ out) {
    int i = blockIdx.x * blockDim.x + threadIdx.x;
    int tot = (nt + 1) * 128 * ncols;
    if (i >= tot) return;
    int blk = i / (128 * ncols);
    if (blk < nt) out[i] = Wl[i];
    else {
        int off = i - nt * 128 * ncols;
        float s = 0.f;
        for (int j = 0; j < nt; j++) s += Wr[j * 128 * ncols + off];
        out[i] = s;
    }
}

// all 6 bias-vector sums at once (1 block, 128 threads)
__global__ void bias_sums(const float* __restrict__ gatB, const float* __restrict__ s2bl,
                          const float* __restrict__ s3bl, float* __restrict__ o) {
    int t = threadIdx.x;
    o[t]       = gatB[t] + gatB[128 + t] + gatB[256 + t];
    o[128 + t] = gatB[384 + t] + gatB[512 + t] + gatB[640 + t];
    o[256 + t] = s2bl[t] + s2bl[128 + t] + s2bl[256 + t];
    o[384 + t] = s2bl[384 + t] + s2bl[512 + t] + s2bl[640 + t];
    if (t < 64) {
        o[512 + t] = s3bl[t] + s3bl[64 + t];
        o[576 + t] = s3bl[128 + t] + s3bl[192 + t];
    }
}

// L2-normalize rows of [N,64] -> out
__global__ void norm_out(const float* __restrict__ X, float* __restrict__ out, int N) {
    int gt = blockIdx.x * blockDim.x + threadIdx.x;
    int w = gt >> 5;
    if (w >= N) return;
    int lane = threadIdx.x & 31;
    float v0 = X[(size_t)w * 64 + lane];
    float v1 = X[(size_t)w * 64 + 32 + lane];
    float ss = v0 * v0 + v1 * v1;
    for (int off = 16; off; off >>= 1) ss += __shfl_xor_sync(0xffffffffu, ss, off);
    float sc = 1.f / fmaxf(sqrtf(ss), 1e-12f);
    out[(size_t)w * 64 + lane] = v0 * sc;
    out[(size_t)w * 64 + 32 + lane] = v1 * sc;
}

// ---------------- host ----------------
static inline int cdiv(int a, int b) { return (a + b - 1) / b; }

extern "C" void kernel_launch(void* const* d_in, const int* in_sizes, int n_in,
                              void* d_out, int out_size) {
    const float* xc    = (const float*)d_in[0];
    const float* xe    = (const float*)d_in[1];
    const float* Wc    = (const float*)d_in[2];
    const float* bc    = (const float*)d_in[3];
    const float* We    = (const float*)d_in[4];
    const float* be    = (const float*)d_in[5];
    const float* gatW  = (const float*)d_in[6];
    const float* gatAs = (const float*)d_in[7];
    const float* gatAd = (const float*)d_in[8];
    const float* gatB  = (const float*)d_in[9];
    const float* s2Wl  = (const float*)d_in[10];
    const float* s2bl  = (const float*)d_in[11];
    const float* s2Wr  = (const float*)d_in[12];
    const float* s3Wl  = (const float*)d_in[13];
    const float* s3bl  = (const float*)d_in[14];
    const float* s3Wr  = (const float*)d_in[15];
    float* out = (float*)d_out;

    void* p;
    cudaGetSymbolAddress(&p, g_hc);    float* hc   = (float*)p;
    cudaGetSymbolAddress(&p, g_he);    float* he   = (float*)p;
    cudaGetSymbolAddress(&p, g_hs0);   float* hs0  = (float*)p;
    cudaGetSymbolAddress(&p, g_hs1);   float* hs1  = (float*)p;
    cudaGetSymbolAddress(&p, g_c1);    float* c1   = (float*)p;
    cudaGetSymbolAddress(&p, g_e1);    float* e1   = (float*)p;
    cudaGetSymbolAddress(&p, g_c2);    float* c2   = (float*)p;
    cudaGetSymbolAddress(&p, g_e2);    float* e2   = (float*)p;
    cudaGetSymbolAddress(&p, g_c3);    float* c3   = (float*)p;
    cudaGetSymbolAddress(&p, g_e3);    float* e3   = (float*)p;
    cudaGetSymbolAddress(&p, g_mcC);   float* mcC  = (float*)p;
    cudaGetSymbolAddress(&p, g_mcE);   float* mcE  = (float*)p;
    cudaGetSymbolAddress(&p, g_asrc6); float* asrc6 = (float*)p;
    cudaGetSymbolAddress(&p, g_adst6); float* adst6 = (float*)p;
    cudaGetSymbolAddress(&p, g_Avs6);  float* Avs6 = (float*)p;
    cudaGetSymbolAddress(&p, g_Avd6);  float* Avd6 = (float*)p;
    cudaGetSymbolAddress(&p, g_bsum);  float* bsum = (float*)p;
    cudaGetSymbolAddress(&p, g_Bc2);   float* Bc2  = (float*)p;
    cudaGetSymbolAddress(&p, g_Be2);   float* Be2  = (float*)p;
    cudaGetSymbolAddress(&p, g_Bc3);   float* Bc3  = (float*)p;
    cudaGetSymbolAddress(&p, g_Be3);   float* Be3  = (float*)p;
    cudaGetSymbolAddress(&p, g_rowptr); int* rowptr0 = (int*)p;
    cudaGetSymbolAddress(&p, g_col);    int* col0    = (int*)p;
    cudaGetSymbolAddress(&p, g_cnt);    int* cnt     = (int*)p;
    cudaGetSymbolAddress(&p, g_bsums);  int* bsums   = (int*)p;

    constexpr int SM128 = 128 * 32 * 8 + 128 * 128 * 4;  // 98304
    constexpr int SM64  = 128 * 32 * 8 + 128 * 64 * 4;   // 65536

    // ---- one-time init (first call is uncaptured) ----
    static bool inited = false;
    static cudaStream_t sA, sB;
    static cudaEvent_t evRoot, evCSR, evG[6], evA[6], evC2, evE2, evFA, evFB;
    if (!inited) {
        cudaStreamCreateWithFlags(&sA, cudaStreamNonBlocking);
        cudaStreamCreateWithFlags(&sB, cudaStreamNonBlocking);
        cudaEventCreateWithFlags(&evRoot, cudaEventDisableTiming);
        cudaEventCreateWithFlags(&evCSR, cudaEventDisableTiming);
        for (int i = 0; i < 6; i++) {
            cudaEventCreateWithFlags(&evG[i], cudaEventDisableTiming);
            cudaEventCreateWithFlags(&evA[i], cudaEventDisableTiming);
        }
        cudaEventCreateWithFlags(&evC2, cudaEventDisableTiming);
        cudaEventCreateWithFlags(&evE2, cudaEventDisableTiming);
        cudaEventCreateWithFlags(&evFA, cudaEventDisableTiming);
        cudaEventCreateWithFlags(&evFB, cudaEventDisableTiming);
        cudaFuncSetAttribute(gemmk<128, 1>, cudaFuncAttributeMaxDynamicSharedMemorySize, SM128);
        cudaFuncSetAttribute(gemmk<128, 4>, cudaFuncAttributeMaxDynamicSharedMemorySize, SM128);
        cudaFuncSetAttribute(gemmk<64, 3>,  cudaFuncAttributeMaxDynamicSharedMemorySize, SM64);
        inited = true;
    }

    // ---- fork ----
    cudaEventRecord(evRoot, 0);
    cudaStreamWaitEvent(sA, evRoot, 0);
    cudaStreamWaitEvent(sB, evRoot, 0);

    // ---- stream B: batched CSR build ----
    P6 ei; Nd6 nds, nbs;
    const int ndArr[6] = {NCn, NCn, NCn, NEn, NEn, NEn};
    for (int t = 0; t < 6; t++) {
        ei.p[t] = (const int*)d_in[16 + t];
        nds.nd[t] = ndArr[t];
        nbs.nd[t] = cdiv(ndArr[t], 1024);
    }
    zero_int<<<cdiv(6 * NEn, 256), 256, 0, sB>>>(cnt, 6 * NEn);
    hist6<<<dim3(cdiv(EE, 256), 6), 256, 0, sB>>>(ei, cnt);
    scan_block6<<<dim3(cdiv(NEn, 1024), 6), 256, 0, sB>>>(cnt, rowptr0, bsums, nds);
    scan_top6<<<6, 256, 0, sB>>>(bsums, nbs);
    scan_add6<<<dim3(cdiv(NEn, 256), 6), 256, 0, sB>>>(rowptr0, bsums, nds);
    zero_int<<<cdiv(6 * NEn, 256), 256, 0, sB>>>(cnt, 6 * NEn);
    fill6<<<dim3(cdiv(EE, 256), 6), 256, 0, sB>>>(ei, rowptr0, cnt, col0);
    cudaEventRecord(evCSR, sB);

    // ---- stream A: encoders, small precompute, B-concat prep ----
    const int HH = H * H, HD2 = H * D;
    encoder<<<cdiv(NCn * 32, 256), 256, 0, sA>>>(xc, Wc, bc, hc, NCn, 5);
    encoder<<<cdiv(NEn * 32, 256), 256, 0, sA>>>(xe, We, be, he, NEn, 4);
    bias_sums<<<1, 128, 0, sA>>>(gatB, s2bl, s3bl, bsum);
    compute_av6<<<6, 512, 0, sA>>>(gatW, gatAs, gatAd, Avs6, Avd6);
    bcat<<<cdiv(512 * 128, 256), 256, 0, sA>>>(s2Wl, s2Wr, 3, 128, Bc2);
    bcat<<<cdiv(512 * 128, 256), 256, 0, sA>>>(s2Wl + 3 * HH, s2Wr + 3 * HH, 3, 128, Be2);
    bcat<<<cdiv(384 * 64, 256), 256, 0, sA>>>(s3Wl, s3Wr, 2, 64, Bc3);
    bcat<<<cdiv(384 * 64, 256), 256, 0, sA>>>(s3Wl + 2 * HD2, s3Wr + 2 * HD2, 2, 64, Be3);

    const float* xsArr[6] = {he, he, he, he, hc, hc};
    const float* xdArr[6] = {hc, hc, hc, he, he, he};
    const int nsArr[6] = {NEn, NEn, NEn, NEn, NCn, NCn};
    MV12 mv;
    for (int t = 0; t < 6; t++) {
        mv.s[t]     = {xsArr[t], Avs6 + t * 512, asrc6 + (size_t)t * NEn * 4, nsArr[t]};
        mv.s[6 + t] = {xdArr[t], Avd6 + t * 512, adst6 + (size_t)t * NEn * 4, ndArr[t]};
    }
    matvec_b<<<dim3(cdiv(NEn * 32, 256), 12), 256, 0, sA>>>(mv);

    // ---- Layer 1: GEMM (sA) overlapped with GAT aggregation (sB) ----
    float* hsb[2] = {hs0, hs1};
    for (int t = 0; t < 6; t++) {
        const float* W = gatW + (size_t)t * HH;
        const float* xs = xsArr[t]; int ns = nsArr[t]; int nd = ndArr[t];
        float* dbuf = (t < 3) ? c1 : e1;
        int flags = (t == 0 || t == 3) ? 0 : 1;
        if (t == 2 || t == 5) flags |= 2;
        const float* bp = (t == 2) ? bsum : bsum + 128;
        if (t >= 2) cudaStreamWaitEvent(sA, evA[t - 2], 0);  // hs buffer free
        gemmk<128, 1><<<cdiv(ns, 64), 256, SM128, sA>>>(nullptr, xs, W, hsb[t & 1], ns,
                                                        nullptr, 0);
        cudaEventRecord(evG[t], sA);
        cudaStreamWaitEvent(sB, evG[t], 0);  // also orders matvec/encoder products
        gat_agg<<<cdiv(nd * 32, 256), 256, 0, sB>>>(rowptr0 + t * (NEn + 1),
                                                    col0 + (size_t)t * EE, hsb[t & 1],
                                                    asrc6 + (size_t)t * NEn * 4,
                                                    adst6 + (size_t)t * NEn * 4,
                                                    dbuf, nd, flags, bp);
        cudaEventRecord(evA[t], sB);
    }

    const int* rp[6]; const int* cl[6];
    for (int t = 0; t < 6; t++) {
        rp[t] = rowptr0 + t * (NEn + 1);
        cl[t] = col0 + (size_t)t * EE;
    }

    // ---- Layer 2 ----
    // c-chain on sA: needs e1/c1 (sB, evA[5] covers both) + CSR
    cudaStreamWaitEvent(sA, evA[5], 0);
    {
        MG g; g.rp[0] = rp[0]; g.rp[1] = rp[1]; g.rp[2] = rp[2];
        g.cl[0] = cl[0]; g.cl[1] = cl[1]; g.cl[2] = cl[2];
        g.src[0] = e1; g.src[1] = e1; g.src[2] = e1;
        mean3<<<cdiv(NCn * 32, 256), 256, 0, sA>>>(g, 3, NCn, mcC);
    }
    gemmk<128, 4><<<cdiv(NCn, 64), 256, SM128, sA>>>(mcC, c1, Bc2, c2, NCn, bsum + 256, 2);
    cudaEventRecord(evC2, sA);
    // e-chain on sB (serial after agg t=5)
    {
        MG g; g.rp[0] = rp[3]; g.rp[1] = rp[4]; g.rp[2] = rp[5];
        g.cl[0] = cl[3]; g.cl[1] = cl[4]; g.cl[2] = cl[5];
        g.src[0] = e1; g.src[1] = c1; g.src[2] = c1;
        mean3<<<cdiv(NEn * 32, 256), 256, 0, sB>>>(g, 3, NEn, mcE);
    }
    gemmk<128, 4><<<cdiv(NEn, 64), 256, SM128, sB>>>(mcE, e1, Be2, e2, NEn, bsum + 384, 2);
    cudaEventRecord(evE2, sB);

    // ---- Layer 3 ----
    // c-chain on sA: gathers e2 (sB)
    cudaStreamWaitEvent(sA, evE2, 0);
    {
        MG g; g.rp[0] = rp[0]; g.rp[1] = rp[1]; g.rp[2] = rp[0];
        g.cl[0] = cl[0]; g.cl[1] = cl[1]; g.cl[2] = cl[0];
        g.src[0] = e2; g.src[1] = e2; g.src[2] = e2;
        mean3<<<cdiv(NCn * 32, 256), 256, 0, sA>>>(g, 2, NCn, mcC);
    }
    gemmk<64, 3><<<cdiv(NCn, 64), 256, SM64, sA>>>(mcC, c2, Bc3, c3, NCn, bsum + 512, 0);
    norm_out<<<cdiv(NCn * 32, 256), 256, 0, sA>>>(c3, out, NCn);
    cudaEventRecord(evFA, sA);
    // e-chain on sB: gathers c2 (sA)
    cudaStreamWaitEvent(sB, evC2, 0);
    {
        MG g; g.rp[0] = rp[3]; g.rp[1] = rp[4]; g.rp[2] = rp[3];
        g.cl[0] = cl[3]; g.cl[1] = cl[4]; g.cl[2] = cl[3];
        g.src[0] = e2; g.src[1] = c2; g.src[2] = e2;
        mean3<<<cdiv(NEn * 32, 256), 256, 0, sB>>>(g, 2, NEn, mcE);
    }
    gemmk<64, 3><<<cdiv(NEn, 64), 256, SM64, sB>>>(mcE, e2, Be3, e3, NEn, bsum + 576, 0);
    norm_out<<<cdiv(NEn * 32, 256), 256, 0, sB>>>(e3, out + (size_t)NCn * D, NEn);
    cudaEventRecord(evFB, sB);

    // ---- join ----
    cudaStreamWaitEvent(0, evFA, 0);
    cudaStreamWaitEvent(0, evFB, 0);
}

// round 8
// speedup vs baseline: 1.7997x; 1.0672x over previous
#include <cuda_runtime.h>
#include <cstdint>
#include <math.h>

#define NCn 100000
#define NEn 150000
#define EE  600000
#define H   128
#define D   64

typedef unsigned long long ull;

// ---------------- device scratch (static, no allocations) ----------------
__device__ float g_hc[NCn * H];
__device__ float g_he[NEn * H];
__device__ float g_hs0[NEn * H];
__device__ float g_hs1[NEn * H];
__device__ float g_hs2[NEn * H];
__device__ float g_hs3[NEn * H];
__device__ float g_hs4[NCn * H];
__device__ float g_hs5[NCn * H];
__device__ float g_c1[NCn * H];
__device__ float g_e1[NEn * H];
__device__ float g_c2[NCn * H];
__device__ float g_e2[NEn * H];
__device__ float g_c3[NCn * D];
__device__ float g_e3[NEn * D];
__device__ float g_mcC[(size_t)NCn * 384];   // concat mean buffer (c side)
__device__ float g_mcE[(size_t)NEn * 384];   // concat mean buffer (e side)
__device__ float g_asrc6[6ul * NEn * 4];
__device__ float g_adst6[6ul * NEn * 4];
__device__ float g_Avs6[6 * 512];
__device__ float g_Avd6[6 * 512];
__device__ float g_bsum[768];                // c1,e1,c2,e2 (128), c3,e3 (64)
__device__ float g_Bc2[512 * 128];
__device__ float g_Be2[512 * 128];
__device__ float g_Bc3[384 * 64];
__device__ float g_Be3[384 * 64];
__device__ int   g_rowptr[6][NEn + 1];
__device__ int   g_col[6][EE];
__device__ int   g_cnt[6 * NEn];
__device__ int   g_bsums[6 * 256];

struct P6  { const int* p[6]; };
struct Nd6 { int nd[6]; };
struct MG  { const int* rp[3]; const int* cl[3]; const float* src[3]; };
struct C4  { float* c[4]; };
struct GA  { const int* rp[3]; const int* cl[3]; const float* hs[3];
             const float* asrc[3]; const float* adst[3]; };

// ---------------- f32x2 helpers ----------------
__device__ __forceinline__ ull dupf(float x) {
    ull r; asm("mov.b64 %0,{%1,%1};" : "=l"(r) : "f"(x)); return r;
}
__device__ __forceinline__ ull fma2(ull a, ull b, ull c) {
    ull d; asm("fma.rn.f32x2 %0,%1,%2,%3;" : "=l"(d) : "l"(a), "l"(b), "l"(c)); return d;
}
__device__ __forceinline__ void unpack2(ull v, float& x, float& y) {
    asm("mov.b64 {%0,%1},%2;" : "=f"(x), "=f"(y) : "l"(v));
}

// =====================================================================
// GEMM (K-concat): C[N,NCOLS] = [Acat|Aself][N,CHUNKS*128]*B[CHUNKS*128,NCOLS]
// =====================================================================
template <int NCOLS, int CHUNKS>
__global__ void __launch_bounds__(256) gemmk(const float* __restrict__ Acat,
                                             const float* __restrict__ Aself,
                                             const float* __restrict__ B,
                                             float* __restrict__ C, int N,
                                             const float* __restrict__ bias,
                                             int flags) {
    constexpr int TM = 64;
    extern __shared__ unsigned char smraw[];
    ull* As2p = reinterpret_cast<ull*>(smraw);
    float* Bs = reinterpret_cast<float*>(smraw + 128 * (TM / 2) * 8);

    const int tid = threadIdx.x;
    const int row0 = blockIdx.x * TM;

    constexpr int TX = NCOLS / 4;
    constexpr int TY = 256 / TX;
    constexpr int RP = TM / TY / 2;
    const int tx = tid % TX;
    const int rp0 = (tid / TX) * RP;

    ull acc[RP][4];
#pragma unroll
    for (int j = 0; j < RP; j++)
#pragma unroll
        for (int c = 0; c < 4; c++) acc[j][c] = 0ull;

    for (int ch = 0; ch < CHUNKS; ch++) {
        if (ch > 0) __syncthreads();
        const float* Bp = B + (size_t)ch * 128 * NCOLS;
        for (int i = tid; i < 128 * NCOLS / 4; i += 256)
            reinterpret_cast<float4*>(Bs)[i] = __ldg(reinterpret_cast<const float4*>(Bp) + i);
        {
            const float* Asrc; int strideA;
            if (ch == CHUNKS - 1) { Asrc = Aself; strideA = 128; }
            else { Asrc = Acat + ch * 128; strideA = (CHUNKS - 1) * 128; }
            float* Af = reinterpret_cast<float*>(As2p);
            for (int i = tid; i < TM * 32; i += 256) {
                int r = i & (TM - 1), kq = i >> 6;
                float4 f = make_float4(0.f, 0.f, 0.f, 0.f);
                if (row0 + r < N)
                    f = __ldg(reinterpret_cast<const float4*>(
                            Asrc + (size_t)(row0 + r) * strideA) + kq);
                Af[(kq * 4 + 0) * TM + r] = f.x;
                Af[(kq * 4 + 1) * TM + r] = f.y;
                Af[(kq * 4 + 2) * TM + r] = f.z;
                Af[(kq * 4 + 3) * TM + r] = f.w;
            }
        }
        __syncthreads();

#pragma unroll 4
        for (int k = 0; k < 128; k++) {
            float4 b = *reinterpret_cast<const float4*>(&Bs[k * NCOLS + tx * 4]);
            ull b0 = dupf(b.x), b1 = dupf(b.y), b2 = dupf(b.z), b3 = dupf(b.w);
            const ull* ap = &As2p[k * (TM / 2) + rp0];
#pragma unroll
            for (int j = 0; j < RP; j++) {
                ull a = ap[j];
                acc[j][0] = fma2(a, b0, acc[j][0]);
                acc[j][1] = fma2(a, b1, acc[j][1]);
                acc[j][2] = fma2(a, b2, acc[j][2]);
                acc[j][3] = fma2(a, b3, acc[j][3]);
            }
        }
    }

    float4 bv = make_float4(0.f, 0.f, 0.f, 0.f);
    if (bias) bv = __ldg(reinterpret_cast<const float4*>(bias) + tx);
#pragma unroll
    for (int j = 0; j < RP; j++) {
        int r = row0 + (rp0 + j) * 2;
        float4 v0, v1;
        unpack2(acc[j][0], v0.x, v1.x);
        unpack2(acc[j][1], v0.y, v1.y);
        unpack2(acc[j][2], v0.z, v1.z);
        unpack2(acc[j][3], v0.w, v1.w);
#pragma unroll
        for (int rr = 0; rr < 2; rr++) {
            int row = r + rr;
            if (row < N) {
                float4 v = rr ? v1 : v0;
                v.x += bv.x; v.y += bv.y; v.z += bv.z; v.w += bv.w;
                if (flags & 2) {
                    v.x = fmaxf(v.x, 0.f); v.y = fmaxf(v.y, 0.f);
                    v.z = fmaxf(v.z, 0.f); v.w = fmaxf(v.w, 0.f);
                }
                reinterpret_cast<float4*>(C + (size_t)row * NCOLS)[tx] = v;
            }
        }
    }
}

// multi-B GEMM: C[y] = A * B[y], y = blockIdx.y (layer-1 projections)
__global__ void __launch_bounds__(256) gemm_y(const float* __restrict__ A,
                                              const float* __restrict__ B6,
                                              C4 cs, int N) {
    constexpr int TM = 64, NCOLS = 128;
    extern __shared__ unsigned char smraw[];
    ull* As2p = reinterpret_cast<ull*>(smraw);
    float* Bs = reinterpret_cast<float*>(smraw + 128 * (TM / 2) * 8);

    const int tid = threadIdx.x;
    const int row0 = blockIdx.x * TM;
    const float* B = B6 + (size_t)blockIdx.y * 128 * 128;
    float* C = cs.c[blockIdx.y];

    for (int i = tid; i < 128 * NCOLS / 4; i += 256)
        reinterpret_cast<float4*>(Bs)[i] = __ldg(reinterpret_cast<const float4*>(B) + i);
    {
        float* Af = reinterpret_cast<float*>(As2p);
        for (int i = tid; i < TM * 32; i += 256) {
            int r = i & (TM - 1), kq = i >> 6;
            float4 f = make_float4(0.f, 0.f, 0.f, 0.f);
            if (row0 + r < N)
                f = __ldg(reinterpret_cast<const float4*>(A + (size_t)(row0 + r) * 128) + kq);
            Af[(kq * 4 + 0) * TM + r] = f.x;
            Af[(kq * 4 + 1) * TM + r] = f.y;
            Af[(kq * 4 + 2) * TM + r] = f.z;
            Af[(kq * 4 + 3) * TM + r] = f.w;
        }
    }
    __syncthreads();

    constexpr int TX = 32, RP = 4;
    const int tx = tid % TX;
    const int rp0 = (tid / TX) * RP;

    ull acc[RP][4];
#pragma unroll
    for (int j = 0; j < RP; j++)
#pragma unroll
        for (int c = 0; c < 4; c++) acc[j][c] = 0ull;

#pragma unroll 4
    for (int k = 0; k < 128; k++) {
        float4 b = *reinterpret_cast<const float4*>(&Bs[k * NCOLS + tx * 4]);
        ull b0 = dupf(b.x), b1 = dupf(b.y), b2 = dupf(b.z), b3 = dupf(b.w);
        const ull* ap = &As2p[k * (TM / 2) + rp0];
#pragma unroll
        for (int j = 0; j < RP; j++) {
            ull a = ap[j];
            acc[j][0] = fma2(a, b0, acc[j][0]);
            acc[j][1] = fma2(a, b1, acc[j][1]);
            acc[j][2] = fma2(a, b2, acc[j][2]);
            acc[j][3] = fma2(a, b3, acc[j][3]);
        }
    }
#pragma unroll
    for (int j = 0; j < RP; j++) {
        int r = row0 + (rp0 + j) * 2;
        float4 v0, v1;
        unpack2(acc[j][0], v0.x, v1.x);
        unpack2(acc[j][1], v0.y, v1.y);
        unpack2(acc[j][2], v0.z, v1.z);
        unpack2(acc[j][3], v0.w, v1.w);
        if (r < N)     reinterpret_cast<float4*>(C + (size_t)r * 128)[tx] = v0;
        if (r + 1 < N) reinterpret_cast<float4*>(C + (size_t)(r + 1) * 128)[tx] = v1;
    }
}

// ---------------- batched CSR build ----------------
__global__ void zero_int(int* p, int n) {
    int i = blockIdx.x * blockDim.x + threadIdx.x;
    if (i < n) p[i] = 0;
}
__global__ void hist6(P6 ei, int* cnt) {
    int t = blockIdx.y;
    int i = blockIdx.x * blockDim.x + threadIdx.x;
    if (i < EE) atomicAdd(&cnt[t * NEn + __ldg(ei.p[t] + EE + i)], 1);
}
__global__ void scan_block6(const int* __restrict__ cnt, int* __restrict__ rowptr,
                            int* __restrict__ bsums, Nd6 nds) {
    __shared__ int sh[256];
    int t = blockIdx.y;
    int nd = nds.nd[t];
    if ((int)blockIdx.x * 1024 >= nd) return;
    const int* c = cnt + t * NEn;
    int* out = rowptr + t * (NEn + 1);
    int tid = threadIdx.x;
    int base = blockIdx.x * 1024 + tid * 4;
    int v0 = 0, v1 = 0, v2 = 0, v3 = 0;
    if (base + 0 < nd) v0 = c[base + 0];
    if (base + 1 < nd) v1 = c[base + 1];
    if (base + 2 < nd) v2 = c[base + 2];
    if (base + 3 < nd) v3 = c[base + 3];
    int ts = v0 + v1 + v2 + v3;
    int val = ts;
    sh[tid] = val; __syncthreads();
    for (int off = 1; off < 256; off <<= 1) {
        int tv = (tid >= off) ? sh[tid - off] : 0;
        __syncthreads();
        val += tv; sh[tid] = val; __syncthreads();
    }
    int excl = val - ts;
    if (base + 0 < nd) out[base + 0] = excl; excl += v0;
    if (base + 1 < nd) out[base + 1] = excl; excl += v1;
    if (base + 2 < nd) out[base + 2] = excl; excl += v2;
    if (base + 3 < nd) out[base + 3] = excl;
    if (tid == 255) bsums[t * 256 + blockIdx.x] = val;
}
__global__ void scan_top6(int* bsums, Nd6 nbs) {
    __shared__ int sh[256];
    int t = blockIdx.x;
    int n = nbs.nd[t];
    int* data = bsums + t * 256;
    int tid = threadIdx.x;
    int base = tid * 4;
    int v0 = 0, v1 = 0, v2 = 0, v3 = 0;
    if (base + 0 < n) v0 = data[base + 0];
    if (base + 1 < n) v1 = data[base + 1];
    if (base + 2 < n) v2 = data[base + 2];
    if (base + 3 < n) v3 = data[base + 3];
    int ts = v0 + v1 + v2 + v3;
    int val = ts;
    sh[tid] = val; __syncthreads();
    for (int off = 1; off < 256; off <<= 1) {
        int tv = (tid >= off) ? sh[tid - off] : 0;
        __syncthreads();
        val += tv; sh[tid] = val; __syncthreads();
    }
    int excl = val - ts;
    if (base + 0 < n) data[base + 0] = excl; excl += v0;
    if (base + 1 < n) data[base + 1] = excl; excl += v1;
    if (base + 2 < n) data[base + 2] = excl; excl += v2;
    if (base + 3 < n) data[base + 3] = excl;
}
__global__ void scan_add6(int* rowptr, const int* __restrict__ bsums, Nd6 nds) {
    int t = blockIdx.y;
    int nd = nds.nd[t];
    int i = blockIdx.x * blockDim.x + threadIdx.x;
    if (i < nd) rowptr[t * (NEn + 1) + i] += bsums[t * 256 + (i >> 10)];
    if (i == 0) rowptr[t * (NEn + 1) + nd] = EE;
}
__global__ void fill6(P6 ei, const int* __restrict__ rowptr, int* pos, int* col) {
    int t = blockIdx.y;
    int i = blockIdx.x * blockDim.x + threadIdx.x;
    if (i < EE) {
        int d = __ldg(ei.p[t] + EE + i);
        int s = __ldg(ei.p[t] + i);
        int p = rowptr[t * (NEn + 1) + d] + atomicAdd(&pos[t * NEn + d], 1);
        col[(size_t)t * EE + p] = s;
    }
}

// ---------------- small precompute ----------------
__global__ void compute_av6(const float* __restrict__ W6, const float* __restrict__ as6,
                            const float* __restrict__ ad6, float* Avs, float* Avd) {
    int t = blockIdx.x;
    const float* W = W6 + (size_t)t * H * H;
    const float* as = as6 + t * 128;
    const float* ad = ad6 + t * 128;
    int i = threadIdx.x;
    int k = i >> 2, h = i & 3;
    float sa = 0.f, sd = 0.f;
    for (int j = 0; j < 32; j++) {
        float w = W[k * H + h * 32 + j];
        sa += w * as[h * 32 + j];
        sd += w * ad[h * 32 + j];
    }
    Avs[t * 512 + k * 4 + h] = sa;
    Avd[t * 512 + k * 4 + h] = sd;
}

// dot of register row (float4/lane) with Av[128][4] -> 4 head values, lane0 stores
__device__ __forceinline__ void att_store(float4 acc, const float* __restrict__ Av,
                                          int lane, float* dst) {
    const float4* m = reinterpret_cast<const float4*>(Av) + lane * 4;
    float4 m0 = __ldg(m + 0), m1 = __ldg(m + 1), m2 = __ldg(m + 2), m3 = __ldg(m + 3);
    float4 p;
    p.x = acc.x * m0.x + acc.y * m1.x + acc.z * m2.x + acc.w * m3.x;
    p.y = acc.x * m0.y + acc.y * m1.y + acc.z * m2.y + acc.w * m3.y;
    p.z = acc.x * m0.z + acc.y * m1.z + acc.z * m2.z + acc.w * m3.z;
    p.w = acc.x * m0.w + acc.y * m1.w + acc.z * m2.w + acc.w * m3.w;
    for (int off = 16; off; off >>= 1) {
        p.x += __shfl_down_sync(0xffffffffu, p.x, off);
        p.y += __shfl_down_sync(0xffffffffu, p.y, off);
        p.z += __shfl_down_sync(0xffffffffu, p.z, off);
        p.w += __shfl_down_sync(0xffffffffu, p.w, off);
    }
    if (lane == 0) *reinterpret_cast<float4*>(dst) = p;
}

// encoder + fused attention dot products.
// kind=0 (hc): adst t=0,1,2 ; asrc t=4,5.  kind=1 (he): asrc t=0..3 ; adst t=3,4,5.
__global__ void encoder(const float* __restrict__ X, const float* __restrict__ W,
                        const float* __restrict__ b, float* __restrict__ out,
                        int N, int inF, int kind,
                        const float* __restrict__ Avs6, const float* __restrict__ Avd6,
                        float* __restrict__ asrc6, float* __restrict__ adst6) {
    int t = blockIdx.x * blockDim.x + threadIdx.x;
    int row = t >> 5, lane = t & 31;
    if (row >= N) return;
    float4 acc = __ldg(reinterpret_cast<const float4*>(b) + lane);
    for (int k = 0; k < inF; k++) {
        float xv = __ldg(&X[(size_t)row * inF + k]);
        float4 wv = __ldg(reinterpret_cast<const float4*>(W) + k * 32 + lane);
        acc.x += xv * wv.x; acc.y += xv * wv.y; acc.z += xv * wv.z; acc.w += xv * wv.w;
    }
    acc.x = fmaxf(acc.x, 0.f); acc.y = fmaxf(acc.y, 0.f);
    acc.z = fmaxf(acc.z, 0.f); acc.w = fmaxf(acc.w, 0.f);
    reinterpret_cast<float4*>(out)[(size_t)row * 32 + lane] = acc;

    if (kind == 1) {
#pragma unroll
        for (int tt = 0; tt < 4; tt++)
            att_store(acc, Avs6 + tt * 512, lane, asrc6 + ((size_t)tt * NEn + row) * 4);
#pragma unroll
        for (int tt = 3; tt < 6; tt++)
            att_store(acc, Avd6 + tt * 512, lane, adst6 + ((size_t)tt * NEn + row) * 4);
    } else {
#pragma unroll
        for (int tt = 0; tt < 3; tt++)
            att_store(acc, Avd6 + tt * 512, lane, adst6 + ((size_t)tt * NEn + row) * 4);
#pragma unroll
        for (int tt = 4; tt < 6; tt++)
            att_store(acc, Avs6 + tt * 512, lane, asrc6 + ((size_t)tt * NEn + row) * 4);
    }
}

// merged single-pass GAT aggregation over 3 edge types; bias+relu; writes out once
__global__ void gat3(GA g, float* __restrict__ out, int nd,
                     const float* __restrict__ bias) {
    int w = (blockIdx.x * blockDim.x + threadIdx.x) >> 5;
    if (w >= nd) return;
    int lane = threadIdx.x & 31;
    int h = lane >> 3;
    float4 tot = make_float4(0.f, 0.f, 0.f, 0.f);
#pragma unroll
    for (int tt = 0; tt < 3; tt++) {
        int s0 = g.rp[tt][w], s1 = g.rp[tt][w + 1];
        float ad = __ldg(&g.adst[tt][(size_t)w * 4 + h]);
        const int* col = g.cl[tt];
        const float* hs = g.hs[tt];
        const float* asr = g.asrc[tt];
        float4 num = make_float4(0.f, 0.f, 0.f, 0.f);
        float den = 0.f;
        for (int e = s0; e < s1; e++) {
            int s = __ldg(&col[e]);
            float x = __ldg(&asr[(size_t)s * 4 + h]) + ad;
            x = (x > 0.f) ? x : 0.2f * x;
            float ex = __expf(x);
            den += ex;
            float4 hv = __ldg(reinterpret_cast<const float4*>(hs + (size_t)s * H) + lane);
            num.x += ex * hv.x; num.y += ex * hv.y;
            num.z += ex * hv.z; num.w += ex * hv.w;
        }
        float rden = (s1 > s0) ? 1.f / den : 0.f;
        tot.x += num.x * rden; tot.y += num.y * rden;
        tot.z += num.z * rden; tot.w += num.w * rden;
    }
    float4 b = __ldg(reinterpret_cast<const float4*>(bias) + lane);
    tot.x = fmaxf(tot.x + b.x, 0.f); tot.y = fmaxf(tot.y + b.y, 0.f);
    tot.z = fmaxf(tot.z + b.z, 0.f); tot.w = fmaxf(tot.w + b.w, 0.f);
    reinterpret_cast<float4*>(out + (size_t)w * H)[lane] = tot;
}

// merged SAGE mean: warp per dst node, nt types -> concat output [nd, nt*128]
__global__ void mean3(MG g, int nt, int nd, float* __restrict__ outCat) {
    int w = (blockIdx.x * blockDim.x + threadIdx.x) >> 5;
    if (w >= nd) return;
    int lane = threadIdx.x & 31;
    int stride = nt * 128;
    for (int tt = 0; tt < nt; tt++) {
        int s0 = g.rp[tt][w], s1 = g.rp[tt][w + 1];
        const float* src = g.src[tt];
        const int* col = g.cl[tt];
        float4 acc = make_float4(0.f, 0.f, 0.f, 0.f);
        for (int e = s0; e < s1; e++) {
            int s = __ldg(&col[e]);
            float4 hv = __ldg(reinterpret_cast<const float4*>(src + (size_t)s * H) + lane);
            acc.x += hv.x; acc.y += hv.y; acc.z += hv.z; acc.w += hv.w;
        }
        float sc = 1.f / fmaxf((float)(s1 - s0), 1.f);
        acc.x *= sc; acc.y *= sc; acc.z *= sc; acc.w *= sc;
        *reinterpret_cast<float4*>(outCat + (size_t)w * stride + tt * 128 + lane * 4) = acc;
    }
}

// B-concat prep: out[(nt+1)*128, ncols] = [Wl_0; ...; Wl_{nt-1}; sum_j Wr_j]
__global__ void bcat(const float* __restrict__ Wl, const float* __restrict__ Wr,
                     int nt, int ncols, float* __restrict__ out) {
    int i = blockIdx.x * blockDim.x + threadIdx.x;
    int tot = (nt + 1) * 128 * ncols;
    if (i >= tot) return;
    int blk = i / (128 * ncols);
    if (blk < nt) out[i] = Wl[i];
    else {
        int off = i - nt * 128 * ncols;
        float s = 0.f;
        for (int j = 0; j < nt; j++) s += Wr[j * 128 * ncols + off];
        out[i] = s;
    }
}

// all 6 bias-vector sums at once (1 block, 128 threads)
__global__ void bias_sums(const float* __restrict__ gatB, const float* __restrict__ s2bl,
                          const float* __restrict__ s3bl, float* __restrict__ o) {
    int t = threadIdx.x;
    o[t]       = gatB[t] + gatB[128 + t] + gatB[256 + t];
    o[128 + t] = gatB[384 + t] + gatB[512 + t] + gatB[640 + t];
    o[256 + t] = s2bl[t] + s2bl[128 + t] + s2bl[256 + t];
    o[384 + t] = s2bl[384 + t] + s2bl[512 + t] + s2bl[640 + t];
    if (t < 64) {
        o[512 + t] = s3bl[t] + s3bl[64 + t];
        o[576 + t] = s3bl[128 + t] + s3bl[192 + t];
    }
}

// L2-normalize rows of [N,64] -> out
__global__ void norm_out(const float* __restrict__ X, float* __restrict__ out, int N) {
    int gt = blockIdx.x * blockDim.x + threadIdx.x;
    int w = gt >> 5;
    if (w >= N) return;
    int lane = threadIdx.x & 31;
    float v0 = X[(size_t)w * 64 + lane];
    float v1 = X[(size_t)w * 64 + 32 + lane];
    float ss = v0 * v0 + v1 * v1;
    for (int off = 16; off; off >>= 1) ss += __shfl_xor_sync(0xffffffffu, ss, off);
    float sc = 1.f / fmaxf(sqrtf(ss), 1e-12f);
    out[(size_t)w * 64 + lane] = v0 * sc;
    out[(size_t)w * 64 + 32 + lane] = v1 * sc;
}

// ---------------- host ----------------
static inline int cdiv(int a, int b) { return (a + b - 1) / b; }

extern "C" void kernel_launch(void* const* d_in, const int* in_sizes, int n_in,
                              void* d_out, int out_size) {
    const float* xc    = (const float*)d_in[0];
    const float* xe    = (const float*)d_in[1];
    const float* Wc    = (const float*)d_in[2];
    const float* bc    = (const float*)d_in[3];
    const float* We    = (const float*)d_in[4];
    const float* be    = (const float*)d_in[5];
    const float* gatW  = (const float*)d_in[6];
    const float* gatAs = (const float*)d_in[7];
    const float* gatAd = (const float*)d_in[8];
    const float* gatB  = (const float*)d_in[9];
    const float* s2Wl  = (const float*)d_in[10];
    const float* s2bl  = (const float*)d_in[11];
    const float* s2Wr  = (const float*)d_in[12];
    const float* s3Wl  = (const float*)d_in[13];
    const float* s3bl  = (const float*)d_in[14];
    const float* s3Wr  = (const float*)d_in[15];
    float* out = (float*)d_out;

    void* p;
    cudaGetSymbolAddress(&p, g_hc);    float* hc   = (float*)p;
    cudaGetSymbolAddress(&p, g_he);    float* he   = (float*)p;
    cudaGetSymbolAddress(&p, g_hs0);   float* hs0  = (float*)p;
    cudaGetSymbolAddress(&p, g_hs1);   float* hs1  = (float*)p;
    cudaGetSymbolAddress(&p, g_hs2);   float* hs2  = (float*)p;
    cudaGetSymbolAddress(&p, g_hs3);   float* hs3  = (float*)p;
    cudaGetSymbolAddress(&p, g_hs4);   float* hs4  = (float*)p;
    cudaGetSymbolAddress(&p, g_hs5);   float* hs5  = (float*)p;
    cudaGetSymbolAddress(&p, g_c1);    float* c1   = (float*)p;
    cudaGetSymbolAddress(&p, g_e1);    float* e1   = (float*)p;
    cudaGetSymbolAddress(&p, g_c2);    float* c2   = (float*)p;
    cudaGetSymbolAddress(&p, g_e2);    float* e2   = (float*)p;
    cudaGetSymbolAddress(&p, g_c3);    float* c3   = (float*)p;
    cudaGetSymbolAddress(&p, g_e3);    float* e3   = (float*)p;
    cudaGetSymbolAddress(&p, g_mcC);   float* mcC  = (float*)p;
    cudaGetSymbolAddress(&p, g_mcE);   float* mcE  = (float*)p;
    cudaGetSymbolAddress(&p, g_asrc6); float* asrc6 = (float*)p;
    cudaGetSymbolAddress(&p, g_adst6); float* adst6 = (float*)p;
    cudaGetSymbolAddress(&p, g_Avs6);  float* Avs6 = (float*)p;
    cudaGetSymbolAddress(&p, g_Avd6);  float* Avd6 = (float*)p;
    cudaGetSymbolAddress(&p, g_bsum);  float* bsum = (float*)p;
    cudaGetSymbolAddress(&p, g_Bc2);   float* Bc2  = (float*)p;
    cudaGetSymbolAddress(&p, g_Be2);   float* Be2  = (float*)p;
    cudaGetSymbolAddress(&p, g_Bc3);   float* Bc3  = (float*)p;
    cudaGetSymbolAddress(&p, g_Be3);   float* Be3  = (float*)p;
    cudaGetSymbolAddress(&p, g_rowptr); int* rowptr0 = (int*)p;
    cudaGetSymbolAddress(&p, g_col);    int* col0    = (int*)p;
    cudaGetSymbolAddress(&p, g_cnt);    int* cnt     = (int*)p;
    cudaGetSymbolAddress(&p, g_bsums);  int* bsums   = (int*)p;

    constexpr int SM128 = 128 * 32 * 8 + 128 * 128 * 4;  // 98304
    constexpr int SM64  = 128 * 32 * 8 + 128 * 64 * 4;   // 65536

    static bool inited = false;
    static cudaStream_t sA, sB;
    static cudaEvent_t evRoot, evCSR, evHc, evGhe, evC1, evE1, evC2, evE2, evFA, evFB;
    if (!inited) {
        cudaStreamCreateWithFlags(&sA, cudaStreamNonBlocking);
        cudaStreamCreateWithFlags(&sB, cudaStreamNonBlocking);
        cudaEventCreateWithFlags(&evRoot, cudaEventDisableTiming);
        cudaEventCreateWithFlags(&evCSR, cudaEventDisableTiming);
        cudaEventCreateWithFlags(&evHc, cudaEventDisableTiming);
        cudaEventCreateWithFlags(&evGhe, cudaEventDisableTiming);
        cudaEventCreateWithFlags(&evC1, cudaEventDisableTiming);
        cudaEventCreateWithFlags(&evE1, cudaEventDisableTiming);
        cudaEventCreateWithFlags(&evC2, cudaEventDisableTiming);
        cudaEventCreateWithFlags(&evE2, cudaEventDisableTiming);
        cudaEventCreateWithFlags(&evFA, cudaEventDisableTiming);
        cudaEventCreateWithFlags(&evFB, cudaEventDisableTiming);
        cudaFuncSetAttribute(gemm_y,       cudaFuncAttributeMaxDynamicSharedMemorySize, SM128);
        cudaFuncSetAttribute(gemmk<128, 4>, cudaFuncAttributeMaxDynamicSharedMemorySize, SM128);
        cudaFuncSetAttribute(gemmk<64, 3>,  cudaFuncAttributeMaxDynamicSharedMemorySize, SM64);
        inited = true;
    }

    // ---- fork ----
    cudaEventRecord(evRoot, 0);
    cudaStreamWaitEvent(sA, evRoot, 0);
    cudaStreamWaitEvent(sB, evRoot, 0);

    // ---- stream B: batched CSR build ----
    P6 ei; Nd6 nds, nbs;
    const int ndArr[6] = {NCn, NCn, NCn, NEn, NEn, NEn};
    for (int t = 0; t < 6; t++) {
        ei.p[t] = (const int*)d_in[16 + t];
        nds.nd[t] = ndArr[t];
        nbs.nd[t] = cdiv(ndArr[t], 1024);
    }
    zero_int<<<cdiv(6 * NEn, 256), 256, 0, sB>>>(cnt, 6 * NEn);
    hist6<<<dim3(cdiv(EE, 256), 6), 256, 0, sB>>>(ei, cnt);
    scan_block6<<<dim3(cdiv(NEn, 1024), 6), 256, 0, sB>>>(cnt, rowptr0, bsums, nds);
    scan_top6<<<6, 256, 0, sB>>>(bsums, nbs);
    scan_add6<<<dim3(cdiv(NEn, 256), 6), 256, 0, sB>>>(rowptr0, bsums, nds);
    zero_int<<<cdiv(6 * NEn, 256), 256, 0, sB>>>(cnt, 6 * NEn);
    fill6<<<dim3(cdiv(EE, 256), 6), 256, 0, sB>>>(ei, rowptr0, cnt, col0);
    cudaEventRecord(evCSR, sB);

    // ---- stream A: precompute, encoders (with fused attention dots), B-prep ----
    const int HH = H * H, HD2 = H * D;
    compute_av6<<<6, 512, 0, sA>>>(gatW, gatAs, gatAd, Avs6, Avd6);
    bias_sums<<<1, 128, 0, sA>>>(gatB, s2bl, s3bl, bsum);
    encoder<<<cdiv(NCn * 32, 256), 256, 0, sA>>>(xc, Wc, bc, hc, NCn, 5, 0,
                                                 Avs6, Avd6, asrc6, adst6);
    cudaEventRecord(evHc, sA);
    encoder<<<cdiv(NEn * 32, 256), 256, 0, sA>>>(xe, We, be, he, NEn, 4, 1,
                                                 Avs6, Avd6, asrc6, adst6);
    bcat<<<cdiv(512 * 128, 256), 256, 0, sA>>>(s2Wl, s2Wr, 3, 128, Bc2);
    bcat<<<cdiv(512 * 128, 256), 256, 0, sA>>>(s2Wl + 3 * HH, s2Wr + 3 * HH, 3, 128, Be2);
    bcat<<<cdiv(384 * 64, 256), 256, 0, sA>>>(s3Wl, s3Wr, 2, 64, Bc3);
    bcat<<<cdiv(384 * 64, 256), 256, 0, sA>>>(s3Wl + 2 * HD2, s3Wr + 2 * HD2, 2, 64, Be3);

    // ---- Layer 1 projections ----
    {
        C4 cs; cs.c[0] = hs0; cs.c[1] = hs1; cs.c[2] = hs2; cs.c[3] = hs3;
        gemm_y<<<dim3(cdiv(NEn, 64), 4), 256, SM128, sA>>>(he, gatW, cs, NEn);
        cudaEventRecord(evGhe, sA);
    }
    {
        C4 cs; cs.c[0] = hs4; cs.c[1] = hs5; cs.c[2] = nullptr; cs.c[3] = nullptr;
        cudaStreamWaitEvent(sB, evHc, 0);
        gemm_y<<<dim3(cdiv(NCn, 64), 2), 256, SM128, sB>>>(hc, gatW + 4ul * HH, cs, NCn);
    }

    const int* rp[6]; const int* cl[6];
    for (int t = 0; t < 6; t++) {
        rp[t] = rowptr0 + t * (NEn + 1);
        cl[t] = col0 + (size_t)t * EE;
    }

    // ---- Layer 1 aggregation (single-pass softmax) ----
    {   // c side on sA: types 0,1,2; hs0-2; needs CSR
        cudaStreamWaitEvent(sA, evCSR, 0);
        GA g;
        for (int i = 0; i < 3; i++) {
            g.rp[i] = rp[i]; g.cl[i] = cl[i];
            g.asrc[i] = asrc6 + (size_t)i * NEn * 4;
            g.adst[i] = adst6 + (size_t)i * NEn * 4;
        }
        g.hs[0] = hs0; g.hs[1] = hs1; g.hs[2] = hs2;
        gat3<<<cdiv(NCn * 32, 256), 256, 0, sA>>>(g, c1, NCn, bsum);
        cudaEventRecord(evC1, sA);
    }
    {   // e side on sB: types 3,4,5; hs3 (from sA), hs4-5 (sB)
        cudaStreamWaitEvent(sB, evGhe, 0);
        GA g;
        for (int i = 0; i < 3; i++) {
            int t = 3 + i;
            g.rp[i] = rp[t]; g.cl[i] = cl[t];
            g.asrc[i] = asrc6 + (size_t)t * NEn * 4;
            g.adst[i] = adst6 + (size_t)t * NEn * 4;
        }
        g.hs[0] = hs3; g.hs[1] = hs4; g.hs[2] = hs5;
        gat3<<<cdiv(NEn * 32, 256), 256, 0, sB>>>(g, e1, NEn, bsum + 128);
        cudaEventRecord(evE1, sB);
    }

    // ---- Layer 2 ----
    cudaStreamWaitEvent(sA, evE1, 0);
    {
        MG g; g.rp[0] = rp[0]; g.rp[1] = rp[1]; g.rp[2] = rp[2];
        g.cl[0] = cl[0]; g.cl[1] = cl[1]; g.cl[2] = cl[2];
        g.src[0] = e1; g.src[1] = e1; g.src[2] = e1;
        mean3<<<cdiv(NCn * 32, 256), 256, 0, sA>>>(g, 3, NCn, mcC);
    }
    gemmk<128, 4><<<cdiv(NCn, 64), 256, SM128, sA>>>(mcC, c1, Bc2, c2, NCn, bsum + 256, 2);
    cudaEventRecord(evC2, sA);

    cudaStreamWaitEvent(sB, evC1, 0);
    {
        MG g; g.rp[0] = rp[3]; g.rp[1] = rp[4]; g.rp[2] = rp[5];
        g.cl[0] = cl[3]; g.cl[1] = cl[4]; g.cl[2] = cl[5];
        g.src[0] = e1; g.src[1] = c1; g.src[2] = c1;
        mean3<<<cdiv(NEn * 32, 256), 256, 0, sB>>>(g, 3, NEn, mcE);
    }
    gemmk<128, 4><<<cdiv(NEn, 64), 256, SM128, sB>>>(mcE, e1, Be2, e2, NEn, bsum + 384, 2);
    cudaEventRecord(evE2, sB);

    // ---- Layer 3 ----
    cudaStreamWaitEvent(sA, evE2, 0);
    {
        MG g; g.rp[0] = rp[0]; g.rp[1] = rp[1]; g.rp[2] = rp[0];
        g.cl[0] = cl[0]; g.cl[1] = cl[1]; g.cl[2] = cl[0];
        g.src[0] = e2; g.src[1] = e2; g.src[2] = e2;
        mean3<<<cdiv(NCn * 32, 256), 256, 0, sA>>>(g, 2, NCn, mcC);
    }
    gemmk<64, 3><<<cdiv(NCn, 64), 256, SM64, sA>>>(mcC, c2, Bc3, c3, NCn, bsum + 512, 0);
    norm_out<<<cdiv(NCn * 32, 256), 256, 0, sA>>>(c3, out, NCn);
    cudaEventRecord(evFA, sA);

    cudaStreamWaitEvent(sB, evC2, 0);
    {
        MG g; g.rp[0] = rp[3]; g.rp[1] = rp[4]; g.rp[2] = rp[3];
        g.cl[0] = cl[3]; g.cl[1] = cl[4]; g.cl[2] = cl[3];
        g.src[0] = e2; g.src[1] = c2; g.src[2] = e2;
        mean3<<<cdiv(NEn * 32, 256), 256, 0, sB>>>(g, 2, NEn, mcE);
    }
    gemmk<64, 3><<<cdiv(NEn, 64), 256, SM64, sB>>>(mcE, e2, Be3, e3, NEn, bsum + 576, 0);
    norm_out<<<cdiv(NEn * 32, 256), 256, 0, sB>>>(e3, out + (size_t)NCn * D, NEn);
    cudaEventRecord(evFB, sB);

    // ---- join ----
    cudaStreamWaitEvent(0, evFA, 0);
    cudaStreamWaitEvent(0, evFB, 0);
}

// round 10
// speedup vs baseline: 1.8275x; 1.0155x over previous
#include <cuda_runtime.h>
#include <cstdint>
#include <math.h>

#define NCn 100000
#define NEn 150000
#define EE  600000
#define H   128
#define D   64

typedef unsigned long long ull;

// ---------------- device scratch (static, no allocations) ----------------
__device__ float g_hc[NCn * H];
__device__ float g_he[NEn * H];
__device__ float g_hs0[NEn * H];
__device__ float g_hs1[NEn * H];
__device__ float g_hs2[NEn * H];
__device__ float g_hs3[NEn * H];
__device__ float g_hs4[NCn * H];
__device__ float g_hs5[NCn * H];
__device__ float g_c1[NCn * H];
__device__ float g_e1[NEn * H];
__device__ float g_c2[NCn * H];
__device__ float g_e2[NEn * H];
__device__ float g_c3[NCn * D];
__device__ float g_e3[NEn * D];
__device__ float g_mcC[(size_t)NCn * 384];
__device__ float g_mcE[(size_t)NEn * 384];
__device__ float g_asrc6[6ul * NEn * 4];
__device__ float g_adst6[6ul * NEn * 4];
__device__ float g_Avs6[6 * 512];
__device__ float g_Avd6[6 * 512];
__device__ float g_bsum[768];
__device__ float g_Bc2[512 * 128];
__device__ float g_Be2[512 * 128];
__device__ float g_Bc3[384 * 64];
__device__ float g_Be3[384 * 64];
__device__ int   g_rowptr[6][NEn + 1];
__device__ int   g_col[6][EE];
__device__ int   g_cnt[6 * NEn];
__device__ int   g_bsums[6 * 256];

struct P6  { const int* p[6]; };
struct Nd6 { int nd[6]; };
struct MG  { const int* rp[3]; const int* cl[3]; const float* src[3]; };
struct C4  { float* c[4]; };
struct GA  { const int* rp[3]; const int* cl[3]; const float* hs[3];
             const float* asrc[3]; const float* adst[3]; };

// ---------------- f32x2 helpers ----------------
__device__ __forceinline__ ull dupf(float x) {
    ull r; asm("mov.b64 %0,{%1,%1};" : "=l"(r) : "f"(x)); return r;
}
__device__ __forceinline__ ull fma2(ull a, ull b, ull c) {
    ull d; asm("fma.rn.f32x2 %0,%1,%2,%3;" : "=l"(d) : "l"(a), "l"(b), "l"(c)); return d;
}
__device__ __forceinline__ void unpack2(ull v, float& x, float& y) {
    asm("mov.b64 {%0,%1},%2;" : "=f"(x), "=f"(y) : "l"(v));
}

// =====================================================================
// GEMM (K-concat): C[N,NCOLS] = [Acat|Aself][N,CHUNKS*128]*B[CHUNKS*128,NCOLS]
// =====================================================================
template <int NCOLS, int CHUNKS>
__global__ void __launch_bounds__(256) gemmk(const float* __restrict__ Acat,
                                             const float* __restrict__ Aself,
                                             const float* __restrict__ B,
                                             float* __restrict__ C, int N,
                                             const float* __restrict__ bias,
                                             int flags) {
    constexpr int TM = 64;
    extern __shared__ unsigned char smraw[];
    ull* As2p = reinterpret_cast<ull*>(smraw);
    float* Bs = reinterpret_cast<float*>(smraw + 128 * (TM / 2) * 8);

    const int tid = threadIdx.x;
    const int row0 = blockIdx.x * TM;

    constexpr int TX = NCOLS / 4;
    constexpr int TY = 256 / TX;
    constexpr int RP = TM / TY / 2;
    const int tx = tid % TX;
    const int rp0 = (tid / TX) * RP;

    ull acc[RP][4];
#pragma unroll
    for (int j = 0; j < RP; j++)
#pragma unroll
        for (int c = 0; c < 4; c++) acc[j][c] = 0ull;

    for (int ch = 0; ch < CHUNKS; ch++) {
        if (ch > 0) __syncthreads();
        const float* Bp = B + (size_t)ch * 128 * NCOLS;
        for (int i = tid; i < 128 * NCOLS / 4; i += 256)
            reinterpret_cast<float4*>(Bs)[i] = __ldg(reinterpret_cast<const float4*>(Bp) + i);
        {
            const float* Asrc; int strideA;
            if (ch == CHUNKS - 1) { Asrc = Aself; strideA = 128; }
            else { Asrc = Acat + ch * 128; strideA = (CHUNKS - 1) * 128; }
            float* Af = reinterpret_cast<float*>(As2p);
            for (int i = tid; i < TM * 32; i += 256) {
                int r = i & (TM - 1), kq = i >> 6;
                float4 f = make_float4(0.f, 0.f, 0.f, 0.f);
                if (row0 + r < N)
                    f = __ldg(reinterpret_cast<const float4*>(
                            Asrc + (size_t)(row0 + r) * strideA) + kq);
                Af[(kq * 4 + 0) * TM + r] = f.x;
                Af[(kq * 4 + 1) * TM + r] = f.y;
                Af[(kq * 4 + 2) * TM + r] = f.z;
                Af[(kq * 4 + 3) * TM + r] = f.w;
            }
        }
        __syncthreads();

#pragma unroll 4
        for (int k = 0; k < 128; k++) {
            float4 b = *reinterpret_cast<const float4*>(&Bs[k * NCOLS + tx * 4]);
            ull b0 = dupf(b.x), b1 = dupf(b.y), b2 = dupf(b.z), b3 = dupf(b.w);
            const ull* ap = &As2p[k * (TM / 2) + rp0];
#pragma unroll
            for (int j = 0; j < RP; j++) {
                ull a = ap[j];
                acc[j][0] = fma2(a, b0, acc[j][0]);
                acc[j][1] = fma2(a, b1, acc[j][1]);
                acc[j][2] = fma2(a, b2, acc[j][2]);
                acc[j][3] = fma2(a, b3, acc[j][3]);
            }
        }
    }

    float4 bv = make_float4(0.f, 0.f, 0.f, 0.f);
    if (bias) bv = __ldg(reinterpret_cast<const float4*>(bias) + tx);
#pragma unroll
    for (int j = 0; j < RP; j++) {
        int r = row0 + (rp0 + j) * 2;
        float4 v0, v1;
        unpack2(acc[j][0], v0.x, v1.x);
        unpack2(acc[j][1], v0.y, v1.y);
        unpack2(acc[j][2], v0.z, v1.z);
        unpack2(acc[j][3], v0.w, v1.w);
#pragma unroll
        for (int rr = 0; rr < 2; rr++) {
            int row = r + rr;
            if (row < N) {
                float4 v = rr ? v1 : v0;
                v.x += bv.x; v.y += bv.y; v.z += bv.z; v.w += bv.w;
                if (flags & 2) {
                    v.x = fmaxf(v.x, 0.f); v.y = fmaxf(v.y, 0.f);
                    v.z = fmaxf(v.z, 0.f); v.w = fmaxf(v.w, 0.f);
                }
                reinterpret_cast<float4*>(C + (size_t)row * NCOLS)[tx] = v;
            }
        }
    }
}

// multi-type projection GEMM: A tile loaded ONCE, loop NT B-matrices in-block.
template <int NT>
__global__ void __launch_bounds__(256) gemm_yt(const float* __restrict__ A,
                                               const float* __restrict__ B6,
                                               C4 cs, int N) {
    constexpr int TM = 64, NCOLS = 128;
    extern __shared__ unsigned char smraw[];
    ull* As2p = reinterpret_cast<ull*>(smraw);
    float* Bs = reinterpret_cast<float*>(smraw + 128 * (TM / 2) * 8);

    const int tid = threadIdx.x;
    const int row0 = blockIdx.x * TM;

    {   // A fill once
        float* Af = reinterpret_cast<float*>(As2p);
        for (int i = tid; i < TM * 32; i += 256) {
            int r = i & (TM - 1), kq = i >> 6;
            float4 f = make_float4(0.f, 0.f, 0.f, 0.f);
            if (row0 + r < N)
                f = __ldg(reinterpret_cast<const float4*>(A + (size_t)(row0 + r) * 128) + kq);
            Af[(kq * 4 + 0) * TM + r] = f.x;
            Af[(kq * 4 + 1) * TM + r] = f.y;
            Af[(kq * 4 + 2) * TM + r] = f.z;
            Af[(kq * 4 + 3) * TM + r] = f.w;
        }
    }

    constexpr int TX = 32, RP = 4;
    const int tx = tid % TX;
    const int rp0 = (tid / TX) * RP;

#pragma unroll 1
    for (int t = 0; t < NT; t++) {
        __syncthreads();  // A ready (t=0) / previous compute done reading Bs
        const float* B = B6 + (size_t)t * 128 * 128;
        for (int i = tid; i < 128 * NCOLS / 4; i += 256)
            reinterpret_cast<float4*>(Bs)[i] = __ldg(reinterpret_cast<const float4*>(B) + i);
        __syncthreads();

        ull acc[RP][4];
#pragma unroll
        for (int j = 0; j < RP; j++)
#pragma unroll
            for (int c = 0; c < 4; c++) acc[j][c] = 0ull;

#pragma unroll 4
        for (int k = 0; k < 128; k++) {
            float4 b = *reinterpret_cast<const float4*>(&Bs[k * NCOLS + tx * 4]);
            ull b0 = dupf(b.x), b1 = dupf(b.y), b2 = dupf(b.z), b3 = dupf(b.w);
            const ull* ap = &As2p[k * (TM / 2) + rp0];
#pragma unroll
            for (int j = 0; j < RP; j++) {
                ull a = ap[j];
                acc[j][0] = fma2(a, b0, acc[j][0]);
                acc[j][1] = fma2(a, b1, acc[j][1]);
                acc[j][2] = fma2(a, b2, acc[j][2]);
                acc[j][3] = fma2(a, b3, acc[j][3]);
            }
        }
        float* C = cs.c[t];
#pragma unroll
        for (int j = 0; j < RP; j++) {
            int r = row0 + (rp0 + j) * 2;
            float4 v0, v1;
            unpack2(acc[j][0], v0.x, v1.x);
            unpack2(acc[j][1], v0.y, v1.y);
            unpack2(acc[j][2], v0.z, v1.z);
            unpack2(acc[j][3], v0.w, v1.w);
            if (r < N)     reinterpret_cast<float4*>(C + (size_t)r * 128)[tx] = v0;
            if (r + 1 < N) reinterpret_cast<float4*>(C + (size_t)(r + 1) * 128)[tx] = v1;
        }
    }
}

// ---------------- batched CSR build ----------------
__global__ void zero_int(int* p, int n) {
    int i = blockIdx.x * blockDim.x + threadIdx.x;
    if (i < n) p[i] = 0;
}
__global__ void hist6(P6 ei, int* cnt) {
    int t = blockIdx.y;
    int i = blockIdx.x * blockDim.x + threadIdx.x;
    if (i < EE) atomicAdd(&cnt[t * NEn + __ldg(ei.p[t] + EE + i)], 1);
}
__global__ void scan_block6(const int* __restrict__ cnt, int* __restrict__ rowptr,
                            int* __restrict__ bsums, Nd6 nds) {
    __shared__ int sh[256];
    int t = blockIdx.y;
    int nd = nds.nd[t];
    if ((int)blockIdx.x * 1024 >= nd) return;
    const int* c = cnt + t * NEn;
    int* out = rowptr + t * (NEn + 1);
    int tid = threadIdx.x;
    int base = blockIdx.x * 1024 + tid * 4;
    int v0 = 0, v1 = 0, v2 = 0, v3 = 0;
    if (base + 0 < nd) v0 = c[base + 0];
    if (base + 1 < nd) v1 = c[base + 1];
    if (base + 2 < nd) v2 = c[base + 2];
    if (base + 3 < nd) v3 = c[base + 3];
    int ts = v0 + v1 + v2 + v3;
    int val = ts;
    sh[tid] = val; __syncthreads();
    for (int off = 1; off < 256; off <<= 1) {
        int tv = (tid >= off) ? sh[tid - off] : 0;
        __syncthreads();
        val += tv; sh[tid] = val; __syncthreads();
    }
    int excl = val - ts;
    if (base + 0 < nd) out[base + 0] = excl; excl += v0;
    if (base + 1 < nd) out[base + 1] = excl; excl += v1;
    if (base + 2 < nd) out[base + 2] = excl; excl += v2;
    if (base + 3 < nd) out[base + 3] = excl;
    if (tid == 255) bsums[t * 256 + blockIdx.x] = val;
}
__global__ void scan_top6(int* bsums, Nd6 nbs) {
    __shared__ int sh[256];
    int t = blockIdx.x;
    int n = nbs.nd[t];
    int* data = bsums + t * 256;
    int tid = threadIdx.x;
    int base = tid * 4;
    int v0 = 0, v1 = 0, v2 = 0, v3 = 0;
    if (base + 0 < n) v0 = data[base + 0];
    if (base + 1 < n) v1 = data[base + 1];
    if (base + 2 < n) v2 = data[base + 2];
    if (base + 3 < n) v3 = data[base + 3];
    int ts = v0 + v1 + v2 + v3;
    int val = ts;
    sh[tid] = val; __syncthreads();
    for (int off = 1; off < 256; off <<= 1) {
        int tv = (tid >= off) ? sh[tid - off] : 0;
        __syncthreads();
        val += tv; sh[tid] = val; __syncthreads();
    }
    int excl = val - ts;
    if (base + 0 < n) data[base + 0] = excl; excl += v0;
    if (base + 1 < n) data[base + 1] = excl; excl += v1;
    if (base + 2 < n) data[base + 2] = excl; excl += v2;
    if (base + 3 < n) data[base + 3] = excl;
}
__global__ void scan_add6(int* rowptr, const int* __restrict__ bsums, Nd6 nds) {
    int t = blockIdx.y;
    int nd = nds.nd[t];
    int i = blockIdx.x * blockDim.x + threadIdx.x;
    if (i < nd) rowptr[t * (NEn + 1) + i] += bsums[t * 256 + (i >> 10)];
    if (i == 0) rowptr[t * (NEn + 1) + nd] = EE;
}
__global__ void fill6(P6 ei, const int* __restrict__ rowptr, int* pos, int* col) {
    int t = blockIdx.y;
    int i = blockIdx.x * blockDim.x + threadIdx.x;
    if (i < EE) {
        int d = __ldg(ei.p[t] + EE + i);
        int s = __ldg(ei.p[t] + i);
        int p = rowptr[t * (NEn + 1) + d] + atomicAdd(&pos[t * NEn + d], 1);
        col[(size_t)t * EE + p] = s;
    }
}

// ---------------- small precompute ----------------
__global__ void compute_av6(const float* __restrict__ W6, const float* __restrict__ as6,
                            const float* __restrict__ ad6, float* Avs, float* Avd) {
    int t = blockIdx.x;
    const float* W = W6 + (size_t)t * H * H;
    const float* as = as6 + t * 128;
    const float* ad = ad6 + t * 128;
    int i = threadIdx.x;
    int k = i >> 2, h = i & 3;
    float sa = 0.f, sd = 0.f;
    for (int j = 0; j < 32; j++) {
        float w = W[k * H + h * 32 + j];
        sa += w * as[h * 32 + j];
        sd += w * ad[h * 32 + j];
    }
    Avs[t * 512 + k * 4 + h] = sa;
    Avd[t * 512 + k * 4 + h] = sd;
}

__device__ __forceinline__ void att_store(float4 acc, const float* __restrict__ Av,
                                          int lane, float* dst) {
    const float4* m = reinterpret_cast<const float4*>(Av) + lane * 4;
    float4 m0 = __ldg(m + 0), m1 = __ldg(m + 1), m2 = __ldg(m + 2), m3 = __ldg(m + 3);
    float4 p;
    p.x = acc.x * m0.x + acc.y * m1.x + acc.z * m2.x + acc.w * m3.x;
    p.y = acc.x * m0.y + acc.y * m1.y + acc.z * m2.y + acc.w * m3.y;
    p.z = acc.x * m0.z + acc.y * m1.z + acc.z * m2.z + acc.w * m3.z;
    p.w = acc.x * m0.w + acc.y * m1.w + acc.z * m2.w + acc.w * m3.w;
    for (int off = 16; off; off >>= 1) {
        p.x += __shfl_down_sync(0xffffffffu, p.x, off);
        p.y += __shfl_down_sync(0xffffffffu, p.y, off);
        p.z += __shfl_down_sync(0xffffffffu, p.z, off);
        p.w += __shfl_down_sync(0xffffffffu, p.w, off);
    }
    if (lane == 0) *reinterpret_cast<float4*>(dst) = p;
}

__global__ void encoder(const float* __restrict__ X, const float* __restrict__ W,
                        const float* __restrict__ b, float* __restrict__ out,
                        int N, int inF, int kind,
                        const float* __restrict__ Avs6, const float* __restrict__ Avd6,
                        float* __restrict__ asrc6, float* __restrict__ adst6) {
    int t = blockIdx.x * blockDim.x + threadIdx.x;
    int row = t >> 5, lane = t & 31;
    if (row >= N) return;
    float4 acc = __ldg(reinterpret_cast<const float4*>(b) + lane);
    for (int k = 0; k < inF; k++) {
        float xv = __ldg(&X[(size_t)row * inF + k]);
        float4 wv = __ldg(reinterpret_cast<const float4*>(W) + k * 32 + lane);
        acc.x += xv * wv.x; acc.y += xv * wv.y; acc.z += xv * wv.z; acc.w += xv * wv.w;
    }
    acc.x = fmaxf(acc.x, 0.f); acc.y = fmaxf(acc.y, 0.f);
    acc.z = fmaxf(acc.z, 0.f); acc.w = fmaxf(acc.w, 0.f);
    reinterpret_cast<float4*>(out)[(size_t)row * 32 + lane] = acc;

    if (kind == 1) {
#pragma unroll
        for (int tt = 0; tt < 4; tt++)
            att_store(acc, Avs6 + tt * 512, lane, asrc6 + ((size_t)tt * NEn + row) * 4);
#pragma unroll
        for (int tt = 3; tt < 6; tt++)
            att_store(acc, Avd6 + tt * 512, lane, adst6 + ((size_t)tt * NEn + row) * 4);
    } else {
#pragma unroll
        for (int tt = 0; tt < 3; tt++)
            att_store(acc, Avd6 + tt * 512, lane, adst6 + ((size_t)tt * NEn + row) * 4);
#pragma unroll
        for (int tt = 4; tt < 6; tt++)
            att_store(acc, Avs6 + tt * 512, lane, asrc6 + ((size_t)tt * NEn + row) * 4);
    }
}

// merged single-pass GAT aggregation over 3 edge types
__global__ void gat3(GA g, float* __restrict__ out, int nd,
                     const float* __restrict__ bias) {
    int w = (blockIdx.x * blockDim.x + threadIdx.x) >> 5;
    if (w >= nd) return;
    int lane = threadIdx.x & 31;
    int h = lane >> 3;
    float4 tot = make_float4(0.f, 0.f, 0.f, 0.f);
#pragma unroll
    for (int tt = 0; tt < 3; tt++) {
        int s0 = g.rp[tt][w], s1 = g.rp[tt][w + 1];
        float ad = __ldg(&g.adst[tt][(size_t)w * 4 + h]);
        const int* col = g.cl[tt];
        const float* hs = g.hs[tt];
        const float* asr = g.asrc[tt];
        float4 num = make_float4(0.f, 0.f, 0.f, 0.f);
        float den = 0.f;
        for (int e = s0; e < s1; e++) {
            int s = __ldg(&col[e]);
            float x = __ldg(&asr[(size_t)s * 4 + h]) + ad;
            x = (x > 0.f) ? x : 0.2f * x;
            float ex = __expf(x);
            den += ex;
            float4 hv = __ldg(reinterpret_cast<const float4*>(hs + (size_t)s * H) + lane);
            num.x += ex * hv.x; num.y += ex * hv.y;
            num.z += ex * hv.z; num.w += ex * hv.w;
        }
        float rden = (s1 > s0) ? 1.f / den : 0.f;
        tot.x += num.x * rden; tot.y += num.y * rden;
        tot.z += num.z * rden; tot.w += num.w * rden;
    }
    float4 b = __ldg(reinterpret_cast<const float4*>(bias) + lane);
    tot.x = fmaxf(tot.x + b.x, 0.f); tot.y = fmaxf(tot.y + b.y, 0.f);
    tot.z = fmaxf(tot.z + b.z, 0.f); tot.w = fmaxf(tot.w + b.w, 0.f);
    reinterpret_cast<float4*>(out + (size_t)w * H)[lane] = tot;
}

// merged SAGE mean: warp per dst node, nt types -> concat output [nd, nt*128]
__global__ void mean3(MG g, int nt, int nd, float* __restrict__ outCat) {
    int w = (blockIdx.x * blockDim.x + threadIdx.x) >> 5;
    if (w >= nd) return;
    int lane = threadIdx.x & 31;
    int stride = nt * 128;
    for (int tt = 0; tt < nt; tt++) {
        int s0 = g.rp[tt][w], s1 = g.rp[tt][w + 1];
        const float* src = g.src[tt];
        const int* col = g.cl[tt];
        float4 acc = make_float4(0.f, 0.f, 0.f, 0.f);
        for (int e = s0; e < s1; e++) {
            int s = __ldg(&col[e]);
            float4 hv = __ldg(reinterpret_cast<const float4*>(src + (size_t)s * H) + lane);
            acc.x += hv.x; acc.y += hv.y; acc.z += hv.z; acc.w += hv.w;
        }
        float sc = 1.f / fmaxf((float)(s1 - s0), 1.f);
        acc.x *= sc; acc.y *= sc; acc.z *= sc; acc.w *= sc;
        *reinterpret_cast<float4*>(outCat + (size_t)w * stride + tt * 128 + lane * 4) = acc;
    }
}

__global__ void bcat(const float* __restrict__ Wl, const float* __restrict__ Wr,
                     int nt, int ncols, float* __restrict__ out) {
    int i = blockIdx.x * blockDim.x + threadIdx.x;
    int tot = (nt + 1) * 128 * ncols;
    if (i >= tot) return;
    int blk = i / (128 * ncols);
    if (blk < nt) out[i] = Wl[i];
    else {
        int off = i - nt * 128 * ncols;
        float s = 0.f;
        for (int j = 0; j < nt; j++) s += Wr[j * 128 * ncols + off];
        out[i] = s;
    }
}

__global__ void bias_sums(const float* __restrict__ gatB, const float* __restrict__ s2bl,
                          const float* __restrict__ s3bl, float* __restrict__ o) {
    int t = threadIdx.x;
    o[t]       = gatB[t] + gatB[128 + t] + gatB[256 + t];
    o[128 + t] = gatB[384 + t] + gatB[512 + t] + gatB[640 + t];
    o[256 + t] = s2bl[t] + s2bl[128 + t] + s2bl[256 + t];
    o[384 + t] = s2bl[384 + t] + s2bl[512 + t] + s2bl[640 + t];
    if (t < 64) {
        o[512 + t] = s3bl[t] + s3bl[64 + t];
        o[576 + t] = s3bl[128 + t] + s3bl[192 + t];
    }
}

__global__ void norm_out(const float* __restrict__ X, float* __restrict__ out, int N) {
    int gt = blockIdx.x * blockDim.x + threadIdx.x;
    int w = gt >> 5;
    if (w >= N) return;
    int lane = threadIdx.x & 31;
    float v0 = X[(size_t)w * 64 + lane];
    float v1 = X[(size_t)w * 64 + 32 + lane];
    float ss = v0 * v0 + v1 * v1;
    for (int off = 16; off; off >>= 1) ss += __shfl_xor_sync(0xffffffffu, ss, off);
    float sc = 1.f / fmaxf(sqrtf(ss), 1e-12f);
    out[(size_t)w * 64 + lane] = v0 * sc;
    out[(size_t)w * 64 + 32 + lane] = v1 * sc;
}

// ---------------- host ----------------
static inline int cdiv(int a, int b) { return (a + b - 1) / b; }

extern "C" void kernel_launch(void* const* d_in, const int* in_sizes, int n_in,
                              void* d_out, int out_size) {
    const float* xc    = (const float*)d_in[0];
    const float* xe    = (const float*)d_in[1];
    const float* Wc    = (const float*)d_in[2];
    const float* bc    = (const float*)d_in[3];
    const float* We    = (const float*)d_in[4];
    const float* be    = (const float*)d_in[5];
    const float* gatW  = (const float*)d_in[6];
    const float* gatAs = (const float*)d_in[7];
    const float* gatAd = (const float*)d_in[8];
    const float* gatB  = (const float*)d_in[9];
    const float* s2Wl  = (const float*)d_in[10];
    const float* s2bl  = (const float*)d_in[11];
    const float* s2Wr  = (const float*)d_in[12];
    const float* s3Wl  = (const float*)d_in[13];
    const float* s3bl  = (const float*)d_in[14];
    const float* s3Wr  = (const float*)d_in[15];
    float* out = (float*)d_out;

    void* p;
    cudaGetSymbolAddress(&p, g_hc);    float* hc   = (float*)p;
    cudaGetSymbolAddress(&p, g_he);    float* he   = (float*)p;
    cudaGetSymbolAddress(&p, g_hs0);   float* hs0  = (float*)p;
    cudaGetSymbolAddress(&p, g_hs1);   float* hs1  = (float*)p;
    cudaGetSymbolAddress(&p, g_hs2);   float* hs2  = (float*)p;
    cudaGetSymbolAddress(&p, g_hs3);   float* hs3  = (float*)p;
    cudaGetSymbolAddress(&p, g_hs4);   float* hs4  = (float*)p;
    cudaGetSymbolAddress(&p, g_hs5);   float* hs5  = (float*)p;
    cudaGetSymbolAddress(&p, g_c1);    float* c1   = (float*)p;
    cudaGetSymbolAddress(&p, g_e1);    float* e1   = (float*)p;
    cudaGetSymbolAddress(&p, g_c2);    float* c2   = (float*)p;
    cudaGetSymbolAddress(&p, g_e2);    float* e2   = (float*)p;
    cudaGetSymbolAddress(&p, g_c3);    float* c3   = (float*)p;
    cudaGetSymbolAddress(&p, g_e3);    float* e3   = (float*)p;
    cudaGetSymbolAddress(&p, g_mcC);   float* mcC  = (float*)p;
    cudaGetSymbolAddress(&p, g_mcE);   float* mcE  = (float*)p;
    cudaGetSymbolAddress(&p, g_asrc6); float* asrc6 = (float*)p;
    cudaGetSymbolAddress(&p, g_adst6); float* adst6 = (float*)p;
    cudaGetSymbolAddress(&p, g_Avs6);  float* Avs6 = (float*)p;
    cudaGetSymbolAddress(&p, g_Avd6);  float* Avd6 = (float*)p;
    cudaGetSymbolAddress(&p, g_bsum);  float* bsum = (float*)p;
    cudaGetSymbolAddress(&p, g_Bc2);   float* Bc2  = (float*)p;
    cudaGetSymbolAddress(&p, g_Be2);   float* Be2  = (float*)p;
    cudaGetSymbolAddress(&p, g_Bc3);   float* Bc3  = (float*)p;
    cudaGetSymbolAddress(&p, g_Be3);   float* Be3  = (float*)p;
    cudaGetSymbolAddress(&p, g_rowptr); int* rowptr0 = (int*)p;
    cudaGetSymbolAddress(&p, g_col);    int* col0    = (int*)p;
    cudaGetSymbolAddress(&p, g_cnt);    int* cnt     = (int*)p;
    cudaGetSymbolAddress(&p, g_bsums);  int* bsums   = (int*)p;

    constexpr int SM128 = 128 * 32 * 8 + 128 * 128 * 4;  // 98304
    constexpr int SM64  = 128 * 32 * 8 + 128 * 64 * 4;   // 65536

    // e-side split points (multiples of 64)
    const int L2B = 89984;             // sB rows in layer-2 e-GEMM
    const int L2A = NEn - L2B;         // sA rows
    const int L3M = 74944;             // sB rows in layer-3 e-chain
    const int L3U = NEn - L3M;         // sA rows

    static bool inited = false;
    static cudaStream_t sA, sB;
    static cudaEvent_t evRoot, evCSR, evHc, evGhe, evC1, evE1, evC2, evME,
                       evE2a, evE2b, evFA, evFB;
    if (!inited) {
        cudaStreamCreateWithFlags(&sA, cudaStreamNonBlocking);
        cudaStreamCreateWithFlags(&sB, cudaStreamNonBlocking);
        cudaEventCreateWithFlags(&evRoot, cudaEventDisableTiming);
        cudaEventCreateWithFlags(&evCSR, cudaEventDisableTiming);
        cudaEventCreateWithFlags(&evHc, cudaEventDisableTiming);
        cudaEventCreateWithFlags(&evGhe, cudaEventDisableTiming);
        cudaEventCreateWithFlags(&evC1, cudaEventDisableTiming);
        cudaEventCreateWithFlags(&evE1, cudaEventDisableTiming);
        cudaEventCreateWithFlags(&evC2, cudaEventDisableTiming);
        cudaEventCreateWithFlags(&evME, cudaEventDisableTiming);
        cudaEventCreateWithFlags(&evE2a, cudaEventDisableTiming);
        cudaEventCreateWithFlags(&evE2b, cudaEventDisableTiming);
        cudaEventCreateWithFlags(&evFA, cudaEventDisableTiming);
        cudaEventCreateWithFlags(&evFB, cudaEventDisableTiming);
        cudaFuncSetAttribute(gemm_yt<4>,    cudaFuncAttributeMaxDynamicSharedMemorySize, SM128);
        cudaFuncSetAttribute(gemm_yt<2>,    cudaFuncAttributeMaxDynamicSharedMemorySize, SM128);
        cudaFuncSetAttribute(gemmk<128, 4>, cudaFuncAttributeMaxDynamicSharedMemorySize, SM128);
        cudaFuncSetAttribute(gemmk<64, 3>,  cudaFuncAttributeMaxDynamicSharedMemorySize, SM64);
        inited = true;
    }

    // ---- fork ----
    cudaEventRecord(evRoot, 0);
    cudaStreamWaitEvent(sA, evRoot, 0);
    cudaStreamWaitEvent(sB, evRoot, 0);

    const int HH = H * H, HD2 = H * D;

    // ---- stream A first: launches #0..#5 (ncu -s 5 profiles launch #5 = gemm_yt<4>)
    compute_av6<<<6, 512, 0, sA>>>(gatW, gatAs, gatAd, Avs6, Avd6);            // 0
    bias_sums<<<1, 128, 0, sA>>>(gatB, s2bl, s3bl, bsum);                      // 1
    encoder<<<cdiv(NCn * 32, 256), 256, 0, sA>>>(xc, Wc, bc, hc, NCn, 5, 0,
                                                 Avs6, Avd6, asrc6, adst6);    // 2
    cudaEventRecord(evHc, sA);
    encoder<<<cdiv(NEn * 32, 256), 256, 0, sA>>>(xe, We, be, he, NEn, 4, 1,
                                                 Avs6, Avd6, asrc6, adst6);    // 3
    bcat<<<cdiv(512 * 128, 256), 256, 0, sA>>>(s2Wl, s2Wr, 3, 128, Bc2);       // 4
    {
        C4 cs; cs.c[0] = hs0; cs.c[1] = hs1; cs.c[2] = hs2; cs.c[3] = hs3;
        gemm_yt<4><<<cdiv(NEn, 64), 256, SM128, sA>>>(he, gatW, cs, NEn);      // 5 <- profiled
        cudaEventRecord(evGhe, sA);
    }
    bcat<<<cdiv(512 * 128, 256), 256, 0, sA>>>(s2Wl + 3 * HH, s2Wr + 3 * HH, 3, 128, Be2);
    bcat<<<cdiv(384 * 64, 256), 256, 0, sA>>>(s3Wl, s3Wr, 2, 64, Bc3);
    bcat<<<cdiv(384 * 64, 256), 256, 0, sA>>>(s3Wl + 2 * HD2, s3Wr + 2 * HD2, 2, 64, Be3);

    // ---- stream B: batched CSR build ----
    P6 ei; Nd6 nds, nbs;
    const int ndArr[6] = {NCn, NCn, NCn, NEn, NEn, NEn};
    for (int t = 0; t < 6; t++) {
        ei.p[t] = (const int*)d_in[16 + t];
        nds.nd[t] = ndArr[t];
        nbs.nd[t] = cdiv(ndArr[t], 1024);
    }
    zero_int<<<cdiv(6 * NEn, 256), 256, 0, sB>>>(cnt, 6 * NEn);
    hist6<<<dim3(cdiv(EE, 256), 6), 256, 0, sB>>>(ei, cnt);
    scan_block6<<<dim3(cdiv(NEn, 1024), 6), 256, 0, sB>>>(cnt, rowptr0, bsums, nds);
    scan_top6<<<6, 256, 0, sB>>>(bsums, nbs);
    scan_add6<<<dim3(cdiv(NEn, 256), 6), 256, 0, sB>>>(rowptr0, bsums, nds);
    zero_int<<<cdiv(6 * NEn, 256), 256, 0, sB>>>(cnt, 6 * NEn);
    fill6<<<dim3(cdiv(EE, 256), 6), 256, 0, sB>>>(ei, rowptr0, cnt, col0);
    cudaEventRecord(evCSR, sB);

    // hc projections on sB
    {
        C4 cs; cs.c[0] = hs4; cs.c[1] = hs5; cs.c[2] = nullptr; cs.c[3] = nullptr;
        cudaStreamWaitEvent(sB, evHc, 0);
        gemm_yt<2><<<cdiv(NCn, 64), 256, SM128, sB>>>(hc, gatW + 4ul * HH, cs, NCn);
    }

    const int* rp[6]; const int* cl[6];
    for (int t = 0; t < 6; t++) {
        rp[t] = rowptr0 + t * (NEn + 1);
        cl[t] = col0 + (size_t)t * EE;
    }

    // ---- Layer 1 aggregation ----
    {   // c side on sA
        cudaStreamWaitEvent(sA, evCSR, 0);
        GA g;
        for (int i = 0; i < 3; i++) {
            g.rp[i] = rp[i]; g.cl[i] = cl[i];
            g.asrc[i] = asrc6 + (size_t)i * NEn * 4;
            g.adst[i] = adst6 + (size_t)i * NEn * 4;
        }
        g.hs[0] = hs0; g.hs[1] = hs1; g.hs[2] = hs2;
        gat3<<<cdiv(NCn * 32, 256), 256, 0, sA>>>(g, c1, NCn, bsum);
        cudaEventRecord(evC1, sA);
    }
    {   // e side on sB
        cudaStreamWaitEvent(sB, evGhe, 0);
        GA g;
        for (int i = 0; i < 3; i++) {
            int t = 3 + i;
            g.rp[i] = rp[t]; g.cl[i] = cl[t];
            g.asrc[i] = asrc6 + (size_t)t * NEn * 4;
            g.adst[i] = adst6 + (size_t)t * NEn * 4;
        }
        g.hs[0] = hs3; g.hs[1] = hs4; g.hs[2] = hs5;
        gat3<<<cdiv(NEn * 32, 256), 256, 0, sB>>>(g, e1, NEn, bsum + 128);
        cudaEventRecord(evE1, sB);
    }

    // ---- Layer 2 ----
    cudaStreamWaitEvent(sA, evE1, 0);
    {
        MG g; g.rp[0] = rp[0]; g.rp[1] = rp[1]; g.rp[2] = rp[2];
        g.cl[0] = cl[0]; g.cl[1] = cl[1]; g.cl[2] = cl[2];
        g.src[0] = e1; g.src[1] = e1; g.src[2] = e1;
        mean3<<<cdiv(NCn * 32, 256), 256, 0, sA>>>(g, 3, NCn, mcC);
    }
    gemmk<128, 4><<<cdiv(NCn, 64), 256, SM128, sA>>>(mcC, c1, Bc2, c2, NCn, bsum + 256, 2);
    cudaEventRecord(evC2, sA);

    cudaStreamWaitEvent(sB, evC1, 0);
    {
        MG g; g.rp[0] = rp[3]; g.rp[1] = rp[4]; g.rp[2] = rp[5];
        g.cl[0] = cl[3]; g.cl[1] = cl[4]; g.cl[2] = cl[5];
        g.src[0] = e1; g.src[1] = c1; g.src[2] = c1;
        mean3<<<cdiv(NEn * 32, 256), 256, 0, sB>>>(g, 3, NEn, mcE);
        cudaEventRecord(evME, sB);
    }
    // e-side layer-2 GEMM split: sB lower rows, sA upper rows
    gemmk<128, 4><<<cdiv(L2B, 64), 256, SM128, sB>>>(mcE, e1, Be2, e2, L2B, bsum + 384, 2);
    cudaEventRecord(evE2b, sB);
    cudaStreamWaitEvent(sA, evME, 0);
    gemmk<128, 4><<<cdiv(L2A, 64), 256, SM128, sA>>>(
        mcE + (size_t)L2B * 384, e1 + (size_t)L2B * 128, Be2,
        e2 + (size_t)L2B * 128, L2A, bsum + 384, 2);
    cudaEventRecord(evE2a, sA);

    // ---- Layer 3 ----
    // c-side on sA (needs full e2: own part ordered, sB part via evE2b)
    cudaStreamWaitEvent(sA, evE2b, 0);
    {
        MG g; g.rp[0] = rp[0]; g.rp[1] = rp[1]; g.rp[2] = rp[0];
        g.cl[0] = cl[0]; g.cl[1] = cl[1]; g.cl[2] = cl[0];
        g.src[0] = e2; g.src[1] = e2; g.src[2] = e2;
        mean3<<<cdiv(NCn * 32, 256), 256, 0, sA>>>(g, 2, NCn, mcC);
    }
    gemmk<64, 3><<<cdiv(NCn, 64), 256, SM64, sA>>>(mcC, c2, Bc3, c3, NCn, bsum + 512, 0);
    norm_out<<<cdiv(NCn * 32, 256), 256, 0, sA>>>(c3, out, NCn);

    // e-side split: sB lower [0, L3M), sA upper [L3M, NEn)
    cudaStreamWaitEvent(sB, evE2a, 0);
    cudaStreamWaitEvent(sB, evC2, 0);
    {
        MG g; g.rp[0] = rp[3]; g.rp[1] = rp[4]; g.rp[2] = rp[3];
        g.cl[0] = cl[3]; g.cl[1] = cl[4]; g.cl[2] = cl[3];
        g.src[0] = e2; g.src[1] = c2; g.src[2] = e2;
        mean3<<<cdiv(L3M * 32, 256), 256, 0, sB>>>(g, 2, L3M, mcE);
    }
    gemmk<64, 3><<<cdiv(L3M, 64), 256, SM64, sB>>>(mcE, e2, Be3, e3, L3M, bsum + 576, 0);
    norm_out<<<cdiv(L3M * 32, 256), 256, 0, sB>>>(e3, out + (size_t)NCn * D, L3M);
    cudaEventRecord(evFB, sB);

    {
        MG g; g.rp[0] = rp[3] + L3M; g.rp[1] = rp[4] + L3M; g.rp[2] = rp[3] + L3M;
        g.cl[0] = cl[3]; g.cl[1] = cl[4]; g.cl[2] = cl[3];
        g.src[0] = e2; g.src[1] = c2; g.src[2] = e2;
        mean3<<<cdiv(L3U * 32, 256), 256, 0, sA>>>(g, 2, L3U, mcE + (size_t)L3M * 256);
    }
    gemmk<64, 3><<<cdiv(L3U, 64), 256, SM64, sA>>>(
        mcE + (size_t)L3M * 256, e2 + (size_t)L3M * 128, Be3,
        e3 + (size_t)L3M * 64, L3U, bsum + 576, 0);
    norm_out<<<cdiv(L3U * 32, 256), 256, 0, sA>>>(e3 + (size_t)L3M * 64,
                                                  out + (size_t)(NCn + L3M) * D, L3U);
    cudaEventRecord(evFA, sA);

    // ---- join ----
    cudaStreamWaitEvent(0, evFA, 0);
    cudaStreamWaitEvent(0, evFB, 0);
}